// round 6
// baseline (speedup 1.0000x reference)
#include <cuda_runtime.h>
#include <cstdint>
#include <cstddef>

#define NN 50000
#define EE 800000

// ---------------- static scratch ----------------
__device__ float g_XNI[(size_t)NN * 128];
__device__ float g_XNJ[(size_t)NN * 128];
__device__ float g_H  [(size_t)NN * 128];
__device__ float g_F1 [(size_t)EE * 128];
__device__ float g_F2 [(size_t)EE * 32];
__device__ float g_X2 [(size_t)NN * 128];
__device__ float g_X3 [(size_t)NN * 32];
__device__ float g_score[EE];
__device__ float g_ex[EE];
__device__ int   g_menc[NN];
__device__ float g_ssum[NN];
// padded layer-2/3 weights (30 -> 32)
__device__ float g_Wni2[128 * 32], g_Wnj2[128 * 32], g_Wn2[128 * 32], g_Wf2[128 * 32];
__device__ float g_bn2[32], g_bias2[32], g_attn2[32];
__device__ float g_Wni3[32 * 64], g_Wnj3[32 * 64], g_Wf3[32 * 64];

// ---------------- fused pad: all param pads in ONE launch ----------------
struct PadJob { const float* in; float* out; int R, C, nR, nC; };
struct PadJobs { PadJob j[10]; };

__global__ void pad_all(PadJobs jobs) {
    PadJob p = jobs.j[blockIdx.y];
    int i = blockIdx.x * blockDim.x + threadIdx.x;
    int tot = p.nR * p.nC;
    if (i >= tot) return;
    int r = i / p.nC, c = i % p.nC;
    p.out[i] = (r < p.R && c < p.C) ? p.in[r * p.C + c] : 0.0f;
}

// ---------------- tf32 helpers ----------------
__device__ __forceinline__ uint32_t f2tf32(float f) {
    uint32_t r;
    asm("cvt.rna.tf32.f32 %0, %1;" : "=r"(r) : "f"(f));
    return r;
}

__device__ __forceinline__ void mma8(float d[4], const uint32_t a[4], const uint32_t b[2]) {
    asm volatile(
        "mma.sync.aligned.m16n8k8.row.col.f32.tf32.tf32.f32 "
        "{%0,%1,%2,%3}, {%4,%5,%6,%7}, {%8,%9}, {%0,%1,%2,%3};\n"
        : "+f"(d[0]), "+f"(d[1]), "+f"(d[2]), "+f"(d[3])
        : "r"(a[0]), "r"(a[1]), "r"(a[2]), "r"(a[3]), "r"(b[0]), "r"(b[1]));
}

// ---------------- 3xTF32 tensor-core GEMM with fused edge epilogue ----------------
// MODE 0: C = A@B (+bias), M guard (node GEMMs)
// MODE 1: F = leaky(A@B + XNI[src] + XNJ[dst] + bias); score = sum(F*attn)
// MODE 2: same, no score (layer 3). For MODE>=1, M % 128 == 0.
// BN == full output width == C row stride. B row stride == BN.
template<int BN, int WM, int WN, int MODE>
__global__ __launch_bounds__(256) void gemm_tf32(
    const float* __restrict__ A, const float* __restrict__ B,
    float* __restrict__ C, const float* __restrict__ bias,
    const float* __restrict__ XNI, const float* __restrict__ XNJ,
    const int* __restrict__ src, const int* __restrict__ dst,
    const float* __restrict__ attn, float* __restrict__ score,
    int M, int K)
{
    constexpr int BM = 128, BK = 16;
    constexpr int MT = WM / 16, NT = WN / 8;
    constexpr int WARPS_N = BN / WN;
    static_assert((BM / WM) * (BN / WN) == 8, "need 8 warps");

    __shared__ uint32_t Ab[BK][BM + 4], Asm[BK][BM + 4];
    __shared__ uint32_t Bb[BK][BN + 4], Bsm[BK][BN + 4];
    __shared__ float s_sc[BM];

    const int tid  = threadIdx.x;
    const int warp = tid >> 5, lane = tid & 31;
    const int gid  = lane >> 2, tig = lane & 3;
    const int wm   = warp / WARPS_N, wn = warp % WARPS_N;
    const int rowW = wm * WM, colW = wn * WN;
    const int row0 = blockIdx.x * BM;

    if (MODE == 1 && tid < BM) s_sc[tid] = 0.0f;

    float acc[MT][NT][4];
    #pragma unroll
    for (int i = 0; i < MT; i++)
        #pragma unroll
        for (int j = 0; j < NT; j++)
            #pragma unroll
            for (int t = 0; t < 4; t++) acc[i][j][t] = 0.0f;

    for (int k0 = 0; k0 < K; k0 += BK) {
        // A tile: BM x BK, stored k-major transposed, split big/small
        #pragma unroll
        for (int v = tid; v < BM * BK / 4; v += 256) {
            int r = v / (BK / 4), p = v % (BK / 4);
            int gr = row0 + r;
            float4 q = make_float4(0.f, 0.f, 0.f, 0.f);
            if (gr < M) q = *(const float4*)&A[(size_t)gr * K + k0 + p * 4];
            float vs[4] = {q.x, q.y, q.z, q.w};
            #pragma unroll
            for (int t = 0; t < 4; t++) {
                uint32_t big = f2tf32(vs[t]);
                Ab[p * 4 + t][r]  = big;
                Asm[p * 4 + t][r] = f2tf32(vs[t] - __uint_as_float(big));
            }
        }
        // B tile: BK x BN
        #pragma unroll
        for (int v = tid; v < BK * BN / 4; v += 256) {
            int r = v / (BN / 4), c = v % (BN / 4);
            float4 q = *(const float4*)&B[(size_t)(k0 + r) * BN + c * 4];
            float vs[4] = {q.x, q.y, q.z, q.w};
            #pragma unroll
            for (int t = 0; t < 4; t++) {
                uint32_t big = f2tf32(vs[t]);
                Bb[r][c * 4 + t]  = big;
                Bsm[r][c * 4 + t] = f2tf32(vs[t] - __uint_as_float(big));
            }
        }
        __syncthreads();

        #pragma unroll
        for (int kk = 0; kk < BK; kk += 8) {
            uint32_t abf[MT][4], asf[MT][4], bbf[NT][2], bsf[NT][2];
            #pragma unroll
            for (int i = 0; i < MT; i++) {
                int r = rowW + i * 16 + gid;
                abf[i][0] = Ab[kk + tig][r];          asf[i][0] = Asm[kk + tig][r];
                abf[i][1] = Ab[kk + tig][r + 8];      asf[i][1] = Asm[kk + tig][r + 8];
                abf[i][2] = Ab[kk + tig + 4][r];      asf[i][2] = Asm[kk + tig + 4][r];
                abf[i][3] = Ab[kk + tig + 4][r + 8];  asf[i][3] = Asm[kk + tig + 4][r + 8];
            }
            #pragma unroll
            for (int j = 0; j < NT; j++) {
                int c = colW + j * 8 + gid;
                bbf[j][0] = Bb[kk + tig][c];      bsf[j][0] = Bsm[kk + tig][c];
                bbf[j][1] = Bb[kk + tig + 4][c];  bsf[j][1] = Bsm[kk + tig + 4][c];
            }
            #pragma unroll
            for (int i = 0; i < MT; i++)
                #pragma unroll
                for (int j = 0; j < NT; j++) {
                    mma8(acc[i][j], abf[i], bbf[j]);
                    mma8(acc[i][j], abf[i], bsf[j]);
                    mma8(acc[i][j], asf[i], bbf[j]);
                }
        }
        __syncthreads();
    }

    // ---------------- epilogue ----------------
    if (MODE == 0) {
        #pragma unroll
        for (int i = 0; i < MT; i++) {
            int gr1 = row0 + rowW + i * 16 + gid;
            int gr2 = gr1 + 8;
            #pragma unroll
            for (int j = 0; j < NT; j++) {
                int c = colW + j * 8 + 2 * tig;
                float b0 = bias ? bias[c] : 0.0f;
                float b1 = bias ? bias[c + 1] : 0.0f;
                if (gr1 < M) {
                    float2 o = make_float2(acc[i][j][0] + b0, acc[i][j][1] + b1);
                    *(float2*)&C[(size_t)gr1 * BN + c] = o;
                }
                if (gr2 < M) {
                    float2 o = make_float2(acc[i][j][2] + b0, acc[i][j][3] + b1);
                    *(float2*)&C[(size_t)gr2 * BN + c] = o;
                }
            }
        }
    } else {
        #pragma unroll
        for (int i = 0; i < MT; i++) {
            int lr1 = rowW + i * 16 + gid;
            int lr2 = lr1 + 8;
            int gr1 = row0 + lr1, gr2 = row0 + lr2;
            int sn1 = src[gr1], dn1 = dst[gr1];
            int sn2 = src[gr2], dn2 = dst[gr2];
            float sc1 = 0.0f, sc2 = 0.0f;
            #pragma unroll
            for (int j = 0; j < NT; j++) {
                int c = colW + j * 8 + 2 * tig;
                float b0 = bias[c], b1 = bias[c + 1];
                float2 xi1 = *(const float2*)&XNI[(size_t)sn1 * BN + c];
                float2 xj1 = *(const float2*)&XNJ[(size_t)dn1 * BN + c];
                float o0 = acc[i][j][0] + xi1.x + xj1.x + b0;
                float o1 = acc[i][j][1] + xi1.y + xj1.y + b1;
                o0 = o0 > 0.f ? o0 : 0.01f * o0;
                o1 = o1 > 0.f ? o1 : 0.01f * o1;
                *(float2*)&C[(size_t)gr1 * BN + c] = make_float2(o0, o1);

                float2 xi2 = *(const float2*)&XNI[(size_t)sn2 * BN + c];
                float2 xj2 = *(const float2*)&XNJ[(size_t)dn2 * BN + c];
                float p0 = acc[i][j][2] + xi2.x + xj2.x + b0;
                float p1 = acc[i][j][3] + xi2.y + xj2.y + b1;
                p0 = p0 > 0.f ? p0 : 0.01f * p0;
                p1 = p1 > 0.f ? p1 : 0.01f * p1;
                *(float2*)&C[(size_t)gr2 * BN + c] = make_float2(p0, p1);

                if (MODE == 1) {
                    float a0 = attn[c], a1 = attn[c + 1];
                    sc1 += o0 * a0 + o1 * a1;
                    sc2 += p0 * a0 + p1 * a1;
                }
            }
            if (MODE == 1) {
                sc1 += __shfl_xor_sync(0xffffffffu, sc1, 1);
                sc1 += __shfl_xor_sync(0xffffffffu, sc1, 2);
                sc2 += __shfl_xor_sync(0xffffffffu, sc2, 1);
                sc2 += __shfl_xor_sync(0xffffffffu, sc2, 2);
                if (tig == 0) {
                    atomicAdd(&s_sc[lr1], sc1);
                    atomicAdd(&s_sc[lr2], sc2);
                }
            }
        }
        if (MODE == 1) {
            __syncthreads();
            if (tid < BM) score[row0 + tid] = s_sc[tid];
        }
    }
}

// ---------------- segment softmax over dst ----------------
__device__ __forceinline__ int enc_f(float f) {
    int i = __float_as_int(f);
    return i >= 0 ? i : (i ^ 0x7fffffff);
}
__device__ __forceinline__ float dec_f(int i) {
    return __int_as_float(i >= 0 ? i : (i ^ 0x7fffffff));
}

__global__ void seg_max(const float* __restrict__ score, const int* __restrict__ dst,
                        int* __restrict__ menc, int E) {
    int e = blockIdx.x * blockDim.x + threadIdx.x;
    if (e >= E) return;
    atomicMax(&menc[dst[e]], enc_f(score[e]));
}

__global__ void seg_expsum(const float* __restrict__ score, const int* __restrict__ dst,
                           const int* __restrict__ menc, float* __restrict__ ex,
                           float* __restrict__ ssum, int E) {
    int e = blockIdx.x * blockDim.x + threadIdx.x;
    if (e >= E) return;
    int d = dst[e];
    float ev = expf(score[e] - dec_f(menc[d]));
    ex[e] = ev;
    atomicAdd(&ssum[d], ev);
}

// ---------------- weighted aggregation: out[dst] += a * H[src] ----------------
template<int DO>
__global__ void aggregate_k(const float* __restrict__ ex, const float* __restrict__ ssum,
                            const float* __restrict__ H, const int* __restrict__ src,
                            const int* __restrict__ dst, float* __restrict__ out, int E) {
    constexpr int L = DO / 4;
    long long gt = (long long)blockIdx.x * blockDim.x + threadIdx.x;
    int e = (int)(gt / L), l = (int)(gt % L);
    if (e >= E) return;
    int dn = dst[e];
    float a = ex[e] / ssum[dn];
    float4 h = *(const float4*)&H[(size_t)src[e] * DO + l * 4];
    float* p = &out[(size_t)dn * DO + l * 4];
    asm volatile("red.global.add.v4.f32 [%0], {%1,%2,%3,%4};"
                 :: "l"(p), "f"(h.x * a), "f"(h.y * a), "f"(h.z * a), "f"(h.w * a)
                 : "memory");
}

// ---------------- host ----------------
extern "C" void kernel_launch(void* const* d_in, const int* in_sizes, int n_in,
                              void* d_out, int out_size) {
    const float* x    = (const float*)d_in[0];
    const float* e    = (const float*)d_in[1];
    const int*   src  = (const int*)d_in[2];
    const int*   dst  = (const int*)d_in[3];

    const float* W_n1  = (const float*)d_in[4];
    const float* b_n1  = (const float*)d_in[5];
    const float* W_ni1 = (const float*)d_in[6];
    const float* W_nj1 = (const float*)d_in[7];
    const float* W_f1  = (const float*)d_in[8];
    const float* attn1 = (const float*)d_in[9];
    const float* bias1 = (const float*)d_in[10];

    const float* W_n2  = (const float*)d_in[11];
    const float* b_n2  = (const float*)d_in[12];
    const float* W_ni2 = (const float*)d_in[13];
    const float* W_nj2 = (const float*)d_in[14];
    const float* W_f2  = (const float*)d_in[15];
    const float* attn2 = (const float*)d_in[16];
    const float* bias2 = (const float*)d_in[17];

    const float* W_ni3 = (const float*)d_in[20];
    const float* W_nj3 = (const float*)d_in[21];
    const float* W_f3  = (const float*)d_in[22];
    const float* bias3 = (const float*)d_in[24];

    float* out = (float*)d_out;

    float *XNI, *XNJ, *H, *F1, *F2, *X2, *X3, *score, *ex, *ssum;
    float *Wni2, *Wnj2, *Wn2, *Wf2, *bn2, *bias2p, *attn2p, *Wni3, *Wnj3, *Wf3;
    int* menc;
    cudaGetSymbolAddress((void**)&XNI, g_XNI);
    cudaGetSymbolAddress((void**)&XNJ, g_XNJ);
    cudaGetSymbolAddress((void**)&H,   g_H);
    cudaGetSymbolAddress((void**)&F1,  g_F1);
    cudaGetSymbolAddress((void**)&F2,  g_F2);
    cudaGetSymbolAddress((void**)&X2,  g_X2);
    cudaGetSymbolAddress((void**)&X3,  g_X3);
    cudaGetSymbolAddress((void**)&score, g_score);
    cudaGetSymbolAddress((void**)&ex,  g_ex);
    cudaGetSymbolAddress((void**)&ssum, g_ssum);
    cudaGetSymbolAddress((void**)&menc, g_menc);
    cudaGetSymbolAddress((void**)&Wni2, g_Wni2);
    cudaGetSymbolAddress((void**)&Wnj2, g_Wnj2);
    cudaGetSymbolAddress((void**)&Wn2,  g_Wn2);
    cudaGetSymbolAddress((void**)&Wf2,  g_Wf2);
    cudaGetSymbolAddress((void**)&bn2,  g_bn2);
    cudaGetSymbolAddress((void**)&bias2p, g_bias2);
    cudaGetSymbolAddress((void**)&attn2p, g_attn2);
    cudaGetSymbolAddress((void**)&Wni3, g_Wni3);
    cudaGetSymbolAddress((void**)&Wnj3, g_Wnj3);
    cudaGetSymbolAddress((void**)&Wf3,  g_Wf3);

    const int Nn = NN, Ee = EE;
    const int nodeGrid = (Nn + 127) / 128;
    const int edgeGrid = Ee / 128;
    const int perThread = (Ee + 255) / 256;

    // ---- one fused pad launch for all layer-2/3 params ----
    PadJobs pj;
    pj.j[0] = {W_ni2, Wni2,  128, 30, 128, 32};
    pj.j[1] = {W_nj2, Wnj2,  128, 30, 128, 32};
    pj.j[2] = {W_n2,  Wn2,   128, 30, 128, 32};
    pj.j[3] = {W_f2,  Wf2,   128, 30, 128, 32};
    pj.j[4] = {b_n2,  bn2,     1, 30,   1, 32};
    pj.j[5] = {bias2, bias2p,  1, 30,   1, 32};
    pj.j[6] = {attn2, attn2p,  1, 30,   1, 32};
    pj.j[7] = {W_ni3, Wni3,   30, 64,  32, 64};
    pj.j[8] = {W_nj3, Wnj3,   30, 64,  32, 64};
    pj.j[9] = {W_f3,  Wf3,    30, 64,  32, 64};
    pad_all<<<dim3(16, 10), 256>>>(pj);

    // ================= Layer 1: di=128, do=128 =================
    gemm_tf32<128, 64, 32, 0><<<nodeGrid, 256>>>(x, W_ni1, XNI, nullptr,
        nullptr, nullptr, nullptr, nullptr, nullptr, nullptr, Nn, 128);
    gemm_tf32<128, 64, 32, 0><<<nodeGrid, 256>>>(x, W_nj1, XNJ, nullptr,
        nullptr, nullptr, nullptr, nullptr, nullptr, nullptr, Nn, 128);
    gemm_tf32<128, 64, 32, 0><<<nodeGrid, 256>>>(x, W_n1, H, b_n1,
        nullptr, nullptr, nullptr, nullptr, nullptr, nullptr, Nn, 128);
    gemm_tf32<128, 64, 32, 1><<<edgeGrid, 256>>>(e, W_f1, F1, bias1,
        XNI, XNJ, src, dst, attn1, score, Ee, 128);

    cudaMemsetAsync(menc, 0x80, (size_t)Nn * sizeof(int), 0);
    cudaMemsetAsync(ssum, 0,    (size_t)Nn * sizeof(float), 0);
    cudaMemsetAsync(X2,   0,    (size_t)Nn * 128 * sizeof(float), 0);
    seg_max<<<perThread, 256>>>(score, dst, menc, Ee);
    seg_expsum<<<perThread, 256>>>(score, dst, menc, ex, ssum, Ee);
    aggregate_k<128><<<((long long)Ee * 32 + 255) / 256, 256>>>(ex, ssum, H, src, dst, X2, Ee);

    // ================= Layer 2: di=128, do=30 (padded 32) =================
    gemm_tf32<32, 16, 32, 0><<<nodeGrid, 256>>>(X2, Wni2, XNI, nullptr,
        nullptr, nullptr, nullptr, nullptr, nullptr, nullptr, Nn, 128);
    gemm_tf32<32, 16, 32, 0><<<nodeGrid, 256>>>(X2, Wnj2, XNJ, nullptr,
        nullptr, nullptr, nullptr, nullptr, nullptr, nullptr, Nn, 128);
    gemm_tf32<32, 16, 32, 0><<<nodeGrid, 256>>>(X2, Wn2, H, bn2,
        nullptr, nullptr, nullptr, nullptr, nullptr, nullptr, Nn, 128);
    gemm_tf32<32, 16, 32, 1><<<edgeGrid, 256>>>(F1, Wf2, F2, bias2p,
        XNI, XNJ, src, dst, attn2p, score, Ee, 128);

    cudaMemsetAsync(menc, 0x80, (size_t)Nn * sizeof(int), 0);
    cudaMemsetAsync(ssum, 0,    (size_t)Nn * sizeof(float), 0);
    cudaMemsetAsync(X3,   0,    (size_t)Nn * 32 * sizeof(float), 0);
    seg_max<<<perThread, 256>>>(score, dst, menc, Ee);
    seg_expsum<<<perThread, 256>>>(score, dst, menc, ex, ssum, Ee);
    aggregate_k<32><<<((long long)Ee * 8 + 255) / 256, 256>>>(ex, ssum, H, src, dst, X3, Ee);

    // ================= Layer 3: di=30 (padded 32), do=64; only f =================
    gemm_tf32<64, 32, 32, 0><<<nodeGrid, 256>>>(X3, Wni3, XNI, nullptr,
        nullptr, nullptr, nullptr, nullptr, nullptr, nullptr, Nn, 32);
    gemm_tf32<64, 32, 32, 0><<<nodeGrid, 256>>>(X3, Wnj3, XNJ, nullptr,
        nullptr, nullptr, nullptr, nullptr, nullptr, nullptr, Nn, 32);
    gemm_tf32<64, 32, 32, 2><<<edgeGrid, 256>>>(F2, Wf3, out, bias3,
        XNI, XNJ, src, dst, nullptr, nullptr, Ee, 32);

    (void)in_sizes; (void)n_in; (void)out_size;
}

// round 7
// speedup vs baseline: 1.0348x; 1.0348x over previous
#include <cuda_runtime.h>
#include <cuda_bf16.h>
#include <cstdint>
#include <cstddef>

#define NN 50000
#define EE 800000

// ---------------- static scratch ----------------
__device__ float g_XNI[(size_t)NN * 128];
__device__ float g_XNJ[(size_t)NN * 128];
__device__ float g_H  [(size_t)NN * 128];
__device__ float g_F1 [(size_t)EE * 128];
__device__ float g_F2 [(size_t)EE * 32];
__device__ float g_X2 [(size_t)NN * 128];
__device__ float g_X3 [(size_t)NN * 32];
__device__ float g_score[EE];
__device__ float g_ex[EE];
__device__ int   g_menc[NN];
__device__ float g_ssum[NN];
// padded layer-2/3 weights (30 -> 32)
__device__ float g_Wni2[128 * 32], g_Wnj2[128 * 32], g_Wn2[128 * 32], g_Wf2[128 * 32];
__device__ float g_bn2[32], g_bias2[32], g_attn2[32];
__device__ float g_Wni3[32 * 64], g_Wnj3[32 * 64], g_Wf3[32 * 64];

// ---------------- fused pad: all param pads in ONE launch ----------------
struct PadJob { const float* in; float* out; int R, C, nR, nC; };
struct PadJobs { PadJob j[10]; };

__global__ void pad_all(PadJobs jobs) {
    PadJob p = jobs.j[blockIdx.y];
    int i = blockIdx.x * blockDim.x + threadIdx.x;
    int tot = p.nR * p.nC;
    if (i >= tot) return;
    int r = i / p.nC, c = i % p.nC;
    p.out[i] = (r < p.R && c < p.C) ? p.in[r * p.C + c] : 0.0f;
}

// ---------------- bf16 helpers ----------------
__device__ __forceinline__ uint32_t pk(float a, float b) {
    __nv_bfloat162 h = __floats2bfloat162_rn(a, b);
    return *(uint32_t*)&h;
}
__device__ __forceinline__ float bfe(float v) {  // v rounded to bf16, back to f32
    return __bfloat162float(__float2bfloat16_rn(v));
}

__device__ __forceinline__ void mma16(float d[4], const uint32_t a[4], const uint32_t b[2]) {
    asm volatile(
        "mma.sync.aligned.m16n8k16.row.col.f32.bf16.bf16.f32 "
        "{%0,%1,%2,%3}, {%4,%5,%6,%7}, {%8,%9}, {%0,%1,%2,%3};\n"
        : "+f"(d[0]), "+f"(d[1]), "+f"(d[2]), "+f"(d[3])
        : "r"(a[0]), "r"(a[1]), "r"(a[2]), "r"(a[3]), "r"(b[0]), "r"(b[1]));
}

// ---------------- bf16x3 tensor-core GEMM with fused edge epilogue ----------------
// MODE 0: C = A@B (+bias), M guard (node GEMMs)
// MODE 1: F = leaky(A@B + XNI[src] + XNJ[dst] + bias); score = sum(F*attn)
// MODE 2: same, no score (layer 3). For MODE>=1, M % 128 == 0.
// BN == full output width == C row stride == B row stride. K % 16 == 0.
template<int BN, int WM, int WN, int MODE>
__global__ __launch_bounds__(256, 2) void gemm_bf16x3(
    const float* __restrict__ A, const float* __restrict__ B,
    float* __restrict__ C, const float* __restrict__ bias,
    const float* __restrict__ XNI, const float* __restrict__ XNJ,
    const int* __restrict__ src, const int* __restrict__ dst,
    const float* __restrict__ attn, float* __restrict__ score,
    int M, int K)
{
    constexpr int BM = 128, BK = 16;
    constexpr int MT = WM / 16, NT = WN / 8;
    constexpr int WARPS_N = BN / WN;
    constexpr int AP = BM + 8, BP = BN + 8;  // pad 8 -> conflict-free frag reads
    static_assert((BM / WM) * (BN / WN) == 8, "need 8 warps");

    __shared__ uint32_t Ahi[8][AP], Alo[8][AP];   // [k-pair][m], bf16x2 along k
    __shared__ uint32_t Bhi[8][BP], Blo[8][BP];   // [k-pair][n]
    __shared__ float s_sc[BM];

    const int tid  = threadIdx.x;
    const int warp = tid >> 5, lane = tid & 31;
    const int gid  = lane >> 2, tig = lane & 3;
    const int wm   = warp / WARPS_N, wn = warp % WARPS_N;
    const int rowW = wm * WM, colW = wn * WN;
    const int row0 = blockIdx.x * BM;

    if (MODE == 1 && tid < BM) s_sc[tid] = 0.0f;

    float acc[MT][NT][4];
    #pragma unroll
    for (int i = 0; i < MT; i++)
        #pragma unroll
        for (int j = 0; j < NT; j++)
            #pragma unroll
            for (int t = 0; t < 4; t++) acc[i][j][t] = 0.0f;

    for (int k0 = 0; k0 < K; k0 += BK) {
        // ---- A tile: BM x BK, split hi/lo, pairs along k ----
        #pragma unroll
        for (int v = tid; v < BM * BK / 4; v += 256) {
            int r = v >> 2, kg = v & 3;
            int gr = row0 + r;
            float4 q = make_float4(0.f, 0.f, 0.f, 0.f);
            if (gr < M) q = *(const float4*)&A[(size_t)gr * K + k0 + kg * 4];
            int p = kg * 2;
            Ahi[p    ][r] = pk(q.x, q.y);
            Alo[p    ][r] = pk(q.x - bfe(q.x), q.y - bfe(q.y));
            Ahi[p + 1][r] = pk(q.z, q.w);
            Alo[p + 1][r] = pk(q.z - bfe(q.z), q.w - bfe(q.w));
        }
        // ---- B tile: BK x BN, pairs along k (load 2 rows) ----
        #pragma unroll
        for (int v = tid; v < (BK / 2) * (BN / 4); v += 256) {
            int pr = v / (BN / 4), c4 = v % (BN / 4);
            const float* bp = &B[(size_t)(k0 + 2 * pr) * BN + c4 * 4];
            float4 q0 = *(const float4*)bp;
            float4 q1 = *(const float4*)(bp + BN);
            uint4 hi, lo;
            hi.x = pk(q0.x, q1.x);  lo.x = pk(q0.x - bfe(q0.x), q1.x - bfe(q1.x));
            hi.y = pk(q0.y, q1.y);  lo.y = pk(q0.y - bfe(q0.y), q1.y - bfe(q1.y));
            hi.z = pk(q0.z, q1.z);  lo.z = pk(q0.z - bfe(q0.z), q1.z - bfe(q1.z));
            hi.w = pk(q0.w, q1.w);  lo.w = pk(q0.w - bfe(q0.w), q1.w - bfe(q1.w));
            *(uint4*)&Bhi[pr][c4 * 4] = hi;
            *(uint4*)&Blo[pr][c4 * 4] = lo;
        }
        __syncthreads();

        // ---- one k16 MMA step per tile ----
        uint32_t ah[MT][4], al[MT][4];
        #pragma unroll
        for (int i = 0; i < MT; i++) {
            int r = rowW + i * 16 + gid;
            ah[i][0] = Ahi[tig][r];         al[i][0] = Alo[tig][r];
            ah[i][1] = Ahi[tig][r + 8];     al[i][1] = Alo[tig][r + 8];
            ah[i][2] = Ahi[tig + 4][r];     al[i][2] = Alo[tig + 4][r];
            ah[i][3] = Ahi[tig + 4][r + 8]; al[i][3] = Alo[tig + 4][r + 8];
        }
        #pragma unroll
        for (int j = 0; j < NT; j++) {
            int c = colW + j * 8 + gid;
            uint32_t bh[2] = { Bhi[tig][c], Bhi[tig + 4][c] };
            uint32_t bl[2] = { Blo[tig][c], Blo[tig + 4][c] };
            #pragma unroll
            for (int i = 0; i < MT; i++) {
                mma16(acc[i][j], ah[i], bh);
                mma16(acc[i][j], ah[i], bl);
                mma16(acc[i][j], al[i], bh);
            }
        }
        __syncthreads();
    }

    // ---------------- epilogue ----------------
    if (MODE == 0) {
        #pragma unroll
        for (int i = 0; i < MT; i++) {
            int gr1 = row0 + rowW + i * 16 + gid;
            int gr2 = gr1 + 8;
            #pragma unroll
            for (int j = 0; j < NT; j++) {
                int c = colW + j * 8 + 2 * tig;
                float b0 = bias ? bias[c] : 0.0f;
                float b1 = bias ? bias[c + 1] : 0.0f;
                if (gr1 < M) {
                    float2 o = make_float2(acc[i][j][0] + b0, acc[i][j][1] + b1);
                    *(float2*)&C[(size_t)gr1 * BN + c] = o;
                }
                if (gr2 < M) {
                    float2 o = make_float2(acc[i][j][2] + b0, acc[i][j][3] + b1);
                    *(float2*)&C[(size_t)gr2 * BN + c] = o;
                }
            }
        }
    } else {
        #pragma unroll
        for (int i = 0; i < MT; i++) {
            int lr1 = rowW + i * 16 + gid;
            int lr2 = lr1 + 8;
            int gr1 = row0 + lr1, gr2 = row0 + lr2;
            int sn1 = src[gr1], dn1 = dst[gr1];
            int sn2 = src[gr2], dn2 = dst[gr2];
            float sc1 = 0.0f, sc2 = 0.0f;
            #pragma unroll
            for (int j = 0; j < NT; j++) {
                int c = colW + j * 8 + 2 * tig;
                float b0 = bias[c], b1 = bias[c + 1];
                float2 xi1 = *(const float2*)&XNI[(size_t)sn1 * BN + c];
                float2 xj1 = *(const float2*)&XNJ[(size_t)dn1 * BN + c];
                float o0 = acc[i][j][0] + xi1.x + xj1.x + b0;
                float o1 = acc[i][j][1] + xi1.y + xj1.y + b1;
                o0 = o0 > 0.f ? o0 : 0.01f * o0;
                o1 = o1 > 0.f ? o1 : 0.01f * o1;
                *(float2*)&C[(size_t)gr1 * BN + c] = make_float2(o0, o1);

                float2 xi2 = *(const float2*)&XNI[(size_t)sn2 * BN + c];
                float2 xj2 = *(const float2*)&XNJ[(size_t)dn2 * BN + c];
                float p0 = acc[i][j][2] + xi2.x + xj2.x + b0;
                float p1 = acc[i][j][3] + xi2.y + xj2.y + b1;
                p0 = p0 > 0.f ? p0 : 0.01f * p0;
                p1 = p1 > 0.f ? p1 : 0.01f * p1;
                *(float2*)&C[(size_t)gr2 * BN + c] = make_float2(p0, p1);

                if (MODE == 1) {
                    float a0 = attn[c], a1 = attn[c + 1];
                    sc1 += o0 * a0 + o1 * a1;
                    sc2 += p0 * a0 + p1 * a1;
                }
            }
            if (MODE == 1) {
                sc1 += __shfl_xor_sync(0xffffffffu, sc1, 1);
                sc1 += __shfl_xor_sync(0xffffffffu, sc1, 2);
                sc2 += __shfl_xor_sync(0xffffffffu, sc2, 1);
                sc2 += __shfl_xor_sync(0xffffffffu, sc2, 2);
                if (tig == 0) {
                    atomicAdd(&s_sc[lr1], sc1);
                    atomicAdd(&s_sc[lr2], sc2);
                }
            }
        }
        if (MODE == 1) {
            __syncthreads();
            if (tid < BM) score[row0 + tid] = s_sc[tid];
        }
    }
}

// ---------------- segment softmax over dst ----------------
__device__ __forceinline__ int enc_f(float f) {
    int i = __float_as_int(f);
    return i >= 0 ? i : (i ^ 0x7fffffff);
}
__device__ __forceinline__ float dec_f(int i) {
    return __int_as_float(i >= 0 ? i : (i ^ 0x7fffffff));
}

__global__ void seg_max(const float* __restrict__ score, const int* __restrict__ dst,
                        int* __restrict__ menc, int E) {
    int e = blockIdx.x * blockDim.x + threadIdx.x;
    if (e >= E) return;
    atomicMax(&menc[dst[e]], enc_f(score[e]));
}

__global__ void seg_expsum(const float* __restrict__ score, const int* __restrict__ dst,
                           const int* __restrict__ menc, float* __restrict__ ex,
                           float* __restrict__ ssum, int E) {
    int e = blockIdx.x * blockDim.x + threadIdx.x;
    if (e >= E) return;
    int d = dst[e];
    float ev = expf(score[e] - dec_f(menc[d]));
    ex[e] = ev;
    atomicAdd(&ssum[d], ev);
}

// ---------------- weighted aggregation: out[dst] += a * H[src] ----------------
template<int DO>
__global__ void aggregate_k(const float* __restrict__ ex, const float* __restrict__ ssum,
                            const float* __restrict__ H, const int* __restrict__ src,
                            const int* __restrict__ dst, float* __restrict__ out, int E) {
    constexpr int L = DO / 4;
    long long gt = (long long)blockIdx.x * blockDim.x + threadIdx.x;
    int e = (int)(gt / L), l = (int)(gt % L);
    if (e >= E) return;
    int dn = dst[e];
    float a = ex[e] / ssum[dn];
    float4 h = *(const float4*)&H[(size_t)src[e] * DO + l * 4];
    float* p = &out[(size_t)dn * DO + l * 4];
    asm volatile("red.global.add.v4.f32 [%0], {%1,%2,%3,%4};"
                 :: "l"(p), "f"(h.x * a), "f"(h.y * a), "f"(h.z * a), "f"(h.w * a)
                 : "memory");
}

// ---------------- host ----------------
extern "C" void kernel_launch(void* const* d_in, const int* in_sizes, int n_in,
                              void* d_out, int out_size) {
    const float* x    = (const float*)d_in[0];
    const float* e    = (const float*)d_in[1];
    const int*   src  = (const int*)d_in[2];
    const int*   dst  = (const int*)d_in[3];

    const float* W_n1  = (const float*)d_in[4];
    const float* b_n1  = (const float*)d_in[5];
    const float* W_ni1 = (const float*)d_in[6];
    const float* W_nj1 = (const float*)d_in[7];
    const float* W_f1  = (const float*)d_in[8];
    const float* attn1 = (const float*)d_in[9];
    const float* bias1 = (const float*)d_in[10];

    const float* W_n2  = (const float*)d_in[11];
    const float* b_n2  = (const float*)d_in[12];
    const float* W_ni2 = (const float*)d_in[13];
    const float* W_nj2 = (const float*)d_in[14];
    const float* W_f2  = (const float*)d_in[15];
    const float* attn2 = (const float*)d_in[16];
    const float* bias2 = (const float*)d_in[17];

    const float* W_ni3 = (const float*)d_in[20];
    const float* W_nj3 = (const float*)d_in[21];
    const float* W_f3  = (const float*)d_in[22];
    const float* bias3 = (const float*)d_in[24];

    float* out = (float*)d_out;

    float *XNI, *XNJ, *H, *F1, *F2, *X2, *X3, *score, *ex, *ssum;
    float *Wni2, *Wnj2, *Wn2, *Wf2, *bn2, *bias2p, *attn2p, *Wni3, *Wnj3, *Wf3;
    int* menc;
    cudaGetSymbolAddress((void**)&XNI, g_XNI);
    cudaGetSymbolAddress((void**)&XNJ, g_XNJ);
    cudaGetSymbolAddress((void**)&H,   g_H);
    cudaGetSymbolAddress((void**)&F1,  g_F1);
    cudaGetSymbolAddress((void**)&F2,  g_F2);
    cudaGetSymbolAddress((void**)&X2,  g_X2);
    cudaGetSymbolAddress((void**)&X3,  g_X3);
    cudaGetSymbolAddress((void**)&score, g_score);
    cudaGetSymbolAddress((void**)&ex,  g_ex);
    cudaGetSymbolAddress((void**)&ssum, g_ssum);
    cudaGetSymbolAddress((void**)&menc, g_menc);
    cudaGetSymbolAddress((void**)&Wni2, g_Wni2);
    cudaGetSymbolAddress((void**)&Wnj2, g_Wnj2);
    cudaGetSymbolAddress((void**)&Wn2,  g_Wn2);
    cudaGetSymbolAddress((void**)&Wf2,  g_Wf2);
    cudaGetSymbolAddress((void**)&bn2,  g_bn2);
    cudaGetSymbolAddress((void**)&bias2p, g_bias2);
    cudaGetSymbolAddress((void**)&attn2p, g_attn2);
    cudaGetSymbolAddress((void**)&Wni3, g_Wni3);
    cudaGetSymbolAddress((void**)&Wnj3, g_Wnj3);
    cudaGetSymbolAddress((void**)&Wf3,  g_Wf3);

    const int Nn = NN, Ee = EE;
    const int nodeGrid = (Nn + 127) / 128;
    const int edgeGrid = Ee / 128;
    const int perThread = (Ee + 255) / 256;

    // ---- one fused pad launch for all layer-2/3 params ----
    PadJobs pj;
    pj.j[0] = {W_ni2, Wni2,  128, 30, 128, 32};
    pj.j[1] = {W_nj2, Wnj2,  128, 30, 128, 32};
    pj.j[2] = {W_n2,  Wn2,   128, 30, 128, 32};
    pj.j[3] = {W_f2,  Wf2,   128, 30, 128, 32};
    pj.j[4] = {b_n2,  bn2,     1, 30,   1, 32};
    pj.j[5] = {bias2, bias2p,  1, 30,   1, 32};
    pj.j[6] = {attn2, attn2p,  1, 30,   1, 32};
    pj.j[7] = {W_ni3, Wni3,   30, 64,  32, 64};
    pj.j[8] = {W_nj3, Wnj3,   30, 64,  32, 64};
    pj.j[9] = {W_f3,  Wf3,    30, 64,  32, 64};
    pad_all<<<dim3(16, 10), 256>>>(pj);

    // ================= Layer 1: di=128, do=128 =================
    gemm_bf16x3<128, 64, 32, 0><<<nodeGrid, 256>>>(x, W_ni1, XNI, nullptr,
        nullptr, nullptr, nullptr, nullptr, nullptr, nullptr, Nn, 128);
    gemm_bf16x3<128, 64, 32, 0><<<nodeGrid, 256>>>(x, W_nj1, XNJ, nullptr,
        nullptr, nullptr, nullptr, nullptr, nullptr, nullptr, Nn, 128);
    gemm_bf16x3<128, 64, 32, 0><<<nodeGrid, 256>>>(x, W_n1, H, b_n1,
        nullptr, nullptr, nullptr, nullptr, nullptr, nullptr, Nn, 128);
    gemm_bf16x3<128, 64, 32, 1><<<edgeGrid, 256>>>(e, W_f1, F1, bias1,
        XNI, XNJ, src, dst, attn1, score, Ee, 128);

    cudaMemsetAsync(menc, 0x80, (size_t)Nn * sizeof(int), 0);
    cudaMemsetAsync(ssum, 0,    (size_t)Nn * sizeof(float), 0);
    cudaMemsetAsync(X2,   0,    (size_t)Nn * 128 * sizeof(float), 0);
    seg_max<<<perThread, 256>>>(score, dst, menc, Ee);
    seg_expsum<<<perThread, 256>>>(score, dst, menc, ex, ssum, Ee);
    aggregate_k<128><<<((long long)Ee * 32 + 255) / 256, 256>>>(ex, ssum, H, src, dst, X2, Ee);

    // ================= Layer 2: di=128, do=30 (padded 32) =================
    gemm_bf16x3<32, 16, 32, 0><<<nodeGrid, 256>>>(X2, Wni2, XNI, nullptr,
        nullptr, nullptr, nullptr, nullptr, nullptr, nullptr, Nn, 128);
    gemm_bf16x3<32, 16, 32, 0><<<nodeGrid, 256>>>(X2, Wnj2, XNJ, nullptr,
        nullptr, nullptr, nullptr, nullptr, nullptr, nullptr, Nn, 128);
    gemm_bf16x3<32, 16, 32, 0><<<nodeGrid, 256>>>(X2, Wn2, H, bn2,
        nullptr, nullptr, nullptr, nullptr, nullptr, nullptr, Nn, 128);
    gemm_bf16x3<32, 16, 32, 1><<<edgeGrid, 256>>>(F1, Wf2, F2, bias2p,
        XNI, XNJ, src, dst, attn2p, score, Ee, 128);

    cudaMemsetAsync(menc, 0x80, (size_t)Nn * sizeof(int), 0);
    cudaMemsetAsync(ssum, 0,    (size_t)Nn * sizeof(float), 0);
    cudaMemsetAsync(X3,   0,    (size_t)Nn * 32 * sizeof(float), 0);
    seg_max<<<perThread, 256>>>(score, dst, menc, Ee);
    seg_expsum<<<perThread, 256>>>(score, dst, menc, ex, ssum, Ee);
    aggregate_k<32><<<((long long)Ee * 8 + 255) / 256, 256>>>(ex, ssum, H, src, dst, X3, Ee);

    // ================= Layer 3: di=30 (padded 32), do=64; only f =================
    gemm_bf16x3<64, 32, 32, 0><<<nodeGrid, 256>>>(X3, Wni3, XNI, nullptr,
        nullptr, nullptr, nullptr, nullptr, nullptr, nullptr, Nn, 32);
    gemm_bf16x3<64, 32, 32, 0><<<nodeGrid, 256>>>(X3, Wnj3, XNJ, nullptr,
        nullptr, nullptr, nullptr, nullptr, nullptr, nullptr, Nn, 32);
    gemm_bf16x3<64, 32, 32, 2><<<edgeGrid, 256>>>(F2, Wf3, out, bias3,
        XNI, XNJ, src, dst, nullptr, nullptr, Ee, 32);

    (void)in_sizes; (void)n_in; (void)out_size;
}

// round 8
// speedup vs baseline: 1.4212x; 1.3734x over previous
#include <cuda_runtime.h>
#include <cuda_bf16.h>
#include <cstdint>
#include <cstddef>

#define NN 50000
#define NNP 50048            // padded to multiple of 128
#define EE 800000

// ---------------- static scratch ----------------
__device__ float g_XNI[(size_t)NN * 128];
__device__ float g_XNJ[(size_t)NN * 128];
__device__ float g_H  [(size_t)NN * 128];
__device__ float g_X2 [(size_t)NN * 128];
__device__ float g_X3 [(size_t)NN * 32];
__device__ float g_score[EE];
__device__ float g_ex[EE];
__device__ int   g_menc[NN];
__device__ float g_ssum[NN];
__device__ float g_bn2[32], g_bias2[32], g_attn2[32];

// bf16 hi/lo plane buffers: [plane][elems]
__device__ __nv_bfloat16 g_xP [2][(size_t)NNP * 128];
__device__ __nv_bfloat16 g_eP [2][(size_t)EE * 128];
__device__ __nv_bfloat16 g_F1P[2][(size_t)EE * 128];
__device__ __nv_bfloat16 g_F2P[2][(size_t)EE * 32];
__device__ __nv_bfloat16 g_X2P[2][(size_t)NNP * 128];
__device__ __nv_bfloat16 g_X3P[2][(size_t)NNP * 32];
// weight plane arena: L1 4x[128][128], L2 4x[32][128], L3 3x[64][32]
#define WL1 (128 * 128)
#define WL2 (32 * 128)
#define WL3 (64 * 32)
__device__ __nv_bfloat16 g_wts[2][4 * WL1 + 4 * WL2 + 3 * WL3];

// ---------------- helpers ----------------
__device__ __forceinline__ uint32_t pk(float a, float b) {
    __nv_bfloat162 h = __floats2bfloat162_rn(a, b);
    return *(uint32_t*)&h;
}
__device__ __forceinline__ float bfe(float v) {
    return __bfloat162float(__float2bfloat16_rn(v));
}
__device__ __forceinline__ void mma16(float d[4], const uint32_t a[4], const uint32_t b[2]) {
    asm volatile(
        "mma.sync.aligned.m16n8k16.row.col.f32.bf16.bf16.f32 "
        "{%0,%1,%2,%3}, {%4,%5,%6,%7}, {%8,%9}, {%0,%1,%2,%3};\n"
        : "+f"(d[0]), "+f"(d[1]), "+f"(d[2]), "+f"(d[3])
        : "r"(a[0]), "r"(a[1]), "r"(a[2]), "r"(a[3]), "r"(b[0]), "r"(b[1]));
}
__device__ __forceinline__ void ldsm4(uint32_t r[4], uint32_t addr) {
    asm volatile("ldmatrix.sync.aligned.m8n8.x4.shared.b16 {%0,%1,%2,%3}, [%4];"
        : "=r"(r[0]), "=r"(r[1]), "=r"(r[2]), "=r"(r[3]) : "r"(addr));
}
__device__ __forceinline__ void ldsm2(uint32_t r[2], uint32_t addr) {
    asm volatile("ldmatrix.sync.aligned.m8n8.x2.shared.b16 {%0,%1}, [%2];"
        : "=r"(r[0]), "=r"(r[1]) : "r"(addr));
}
__device__ __forceinline__ void cpa16(uint32_t saddr, const void* g) {
    asm volatile("cp.async.ca.shared.global [%0], [%1], 16;" :: "r"(saddr), "l"(g));
}

// ---------------- converters ----------------
// rows: f32 [R][K] -> hi/lo planes [Rp][K] (zero pad rows). K % 8 == 0.
__global__ void conv_rows(const float* __restrict__ in, __nv_bfloat16* __restrict__ hi,
                          __nv_bfloat16* __restrict__ lo, int R, int K8, int Rp) {
    int i = blockIdx.x * blockDim.x + threadIdx.x;
    if (i >= Rp * K8) return;
    int r = i / K8, c = (i % K8) * 8;
    int K = K8 * 8;
    float v[8] = {};
    if (r < R) {
        float4 a = *(const float4*)&in[(size_t)r * K + c];
        float4 b = *(const float4*)&in[(size_t)r * K + c + 4];
        v[0] = a.x; v[1] = a.y; v[2] = a.z; v[3] = a.w;
        v[4] = b.x; v[5] = b.y; v[6] = b.z; v[7] = b.w;
    }
    __nv_bfloat16 h[8], l[8];
    #pragma unroll
    for (int t = 0; t < 8; t++) {
        h[t] = __float2bfloat16_rn(v[t]);
        l[t] = __float2bfloat16_rn(v[t] - __bfloat162float(h[t]));
    }
    *(uint4*)&hi[(size_t)r * K + c] = *(uint4*)h;
    *(uint4*)&lo[(size_t)r * K + c] = *(uint4*)l;
}

// weights: f32 [K][N] -> transposed planes [Np][Kp] (zero pad)
struct WJob { const float* w; int off, K, N, Kp, Np; };
struct WJobs { WJob j[11]; };
__global__ void conv_wt(WJobs js, __nv_bfloat16* hiB, __nv_bfloat16* loB) {
    WJob jb = js.j[blockIdx.y];
    int i = blockIdx.x * blockDim.x + threadIdx.x;
    if (i >= jb.Np * jb.Kp) return;
    int n = i / jb.Kp, k = i % jb.Kp;
    float v = (n < jb.N && k < jb.K) ? jb.w[k * jb.N + n] : 0.0f;
    __nv_bfloat16 h = __float2bfloat16_rn(v);
    hiB[jb.off + i] = h;
    loB[jb.off + i] = __float2bfloat16_rn(v - __bfloat162float(h));
}

// pad small f32 vectors (30 -> 32)
struct VJob { const float* in; float* out; int C, nC; };
struct VJobs { VJob j[3]; };
__global__ void pad_vec(VJobs js) {
    VJob p = js.j[blockIdx.y];
    int i = threadIdx.x;
    if (i < p.nC) p.out[i] = (i < p.C) ? p.in[i] : 0.0f;
}

// ---------------- plane GEMM: cp.async + ldmatrix + bf16x3 ----------------
// MODE 0: C(f32, stride BN) = A@B (+bias), row guard on stores
// MODE 1: F planes = split(leaky(A@B + XNI[src] + XNJ[dst] + bias)); score
// MODE 2: C(f32) = leaky(...) (layer 3, no score). MODE>=1: M % 128 == 0.
template<int BN, int WM, int WN, int MODE>
__global__ __launch_bounds__(256, 2) void gemm_pl(
    const __nv_bfloat16* __restrict__ Ahi, const __nv_bfloat16* __restrict__ Alo,
    const __nv_bfloat16* __restrict__ Bhi, const __nv_bfloat16* __restrict__ Blo,
    float* __restrict__ C, __nv_bfloat16* __restrict__ Fhi, __nv_bfloat16* __restrict__ Flo,
    const float* __restrict__ bias,
    const float* __restrict__ XNI, const float* __restrict__ XNJ,
    const int* __restrict__ src, const int* __restrict__ dst,
    const float* __restrict__ attn, float* __restrict__ score,
    int M, int K)
{
    constexpr int BM = 128;
    constexpr int MT = WM / 16, NT = WN / 8;
    constexpr int WARPS_N = BN / WN;
    static_assert((BM / WM) * (BN / WN) == 8, "need 8 warps");

    // 48-byte row stride (24 bf16): conflict-free ldmatrix
    __shared__ __align__(16) __nv_bfloat16 sA[2][BM][24];
    __shared__ __align__(16) __nv_bfloat16 sB[2][BN][24];
    __shared__ float s_sc[BM];

    const int tid  = threadIdx.x;
    const int warp = tid >> 5, lane = tid & 31;
    const int gid  = lane >> 2, tig = lane & 3;
    const int wm   = warp / WARPS_N, wn = warp % WARPS_N;
    const int rowW = wm * WM, colW = wn * WN;
    const int row0 = blockIdx.x * BM;

    const uint32_t aBase = (uint32_t)__cvta_generic_to_shared(&sA[0][0][0]);
    const uint32_t bBase = (uint32_t)__cvta_generic_to_shared(&sB[0][0][0]);

    if (MODE == 1 && tid < BM) s_sc[tid] = 0.0f;

    float acc[MT][NT][4];
    #pragma unroll
    for (int i = 0; i < MT; i++)
        #pragma unroll
        for (int j = 0; j < NT; j++)
            #pragma unroll
            for (int t = 0; t < 4; t++) acc[i][j][t] = 0.0f;

    // ldmatrix lane addressing
    const int lrA = lane & 15;
    const int kofA = ((lane >> 4) & 1) * 16;   // bytes
    const int lrB = lane & 7;
    const int kofB = ((lane >> 3) & 1) * 16;

    for (int k0 = 0; k0 < K; k0 += 16) {
        // async tile fill from planes (16B chunks)
        #pragma unroll
        for (int c = tid; c < (BM + BN) * 4; c += 256) {
            int half = c & 1, pl = (c >> 1) & 1, r = c >> 2;
            if (r < BM) {
                const __nv_bfloat16* g = (pl ? Alo : Ahi) + (size_t)(row0 + r) * K + k0 + half * 8;
                cpa16(aBase + (uint32_t)((pl * BM + r) * 48 + half * 16), g);
            } else {
                int n = r - BM;
                const __nv_bfloat16* g = (pl ? Blo : Bhi) + (size_t)n * K + k0 + half * 8;
                cpa16(bBase + (uint32_t)((pl * BN + n) * 48 + half * 16), g);
            }
        }
        asm volatile("cp.async.commit_group;");
        asm volatile("cp.async.wait_group 0;" ::: "memory");
        __syncthreads();

        uint32_t ah[MT][4], al[MT][4];
        #pragma unroll
        for (int i = 0; i < MT; i++) {
            uint32_t ra = aBase + (uint32_t)((rowW + i * 16 + lrA) * 48) + kofA;
            ldsm4(ah[i], ra);
            ldsm4(al[i], ra + (uint32_t)(BM * 48));
        }
        #pragma unroll
        for (int j = 0; j < NT; j++) {
            uint32_t rb = bBase + (uint32_t)((colW + j * 8 + lrB) * 48) + kofB;
            uint32_t bh[2], bl[2];
            ldsm2(bh, rb);
            ldsm2(bl, rb + (uint32_t)(BN * 48));
            #pragma unroll
            for (int i = 0; i < MT; i++) {
                mma16(acc[i][j], ah[i], bh);
                mma16(acc[i][j], ah[i], bl);
                mma16(acc[i][j], al[i], bh);
            }
        }
        __syncthreads();
    }

    // ---------------- epilogue ----------------
    if (MODE == 0) {
        #pragma unroll
        for (int i = 0; i < MT; i++) {
            int gr1 = row0 + rowW + i * 16 + gid;
            int gr2 = gr1 + 8;
            #pragma unroll
            for (int j = 0; j < NT; j++) {
                int c = colW + j * 8 + 2 * tig;
                float b0 = bias ? bias[c] : 0.0f;
                float b1 = bias ? bias[c + 1] : 0.0f;
                if (gr1 < M)
                    *(float2*)&C[(size_t)gr1 * BN + c] =
                        make_float2(acc[i][j][0] + b0, acc[i][j][1] + b1);
                if (gr2 < M)
                    *(float2*)&C[(size_t)gr2 * BN + c] =
                        make_float2(acc[i][j][2] + b0, acc[i][j][3] + b1);
            }
        }
    } else {
        #pragma unroll
        for (int i = 0; i < MT; i++) {
            int lr1 = rowW + i * 16 + gid, lr2 = lr1 + 8;
            int gr1 = row0 + lr1, gr2 = row0 + lr2;
            int sn1 = src[gr1], dn1 = dst[gr1];
            int sn2 = src[gr2], dn2 = dst[gr2];
            float sc1 = 0.0f, sc2 = 0.0f;
            #pragma unroll
            for (int j = 0; j < NT; j++) {
                int c = colW + j * 8 + 2 * tig;
                float b0 = bias[c], b1 = bias[c + 1];
                float2 xi1 = *(const float2*)&XNI[(size_t)sn1 * BN + c];
                float2 xj1 = *(const float2*)&XNJ[(size_t)dn1 * BN + c];
                float o0 = acc[i][j][0] + xi1.x + xj1.x + b0;
                float o1 = acc[i][j][1] + xi1.y + xj1.y + b1;
                o0 = o0 > 0.f ? o0 : 0.01f * o0;
                o1 = o1 > 0.f ? o1 : 0.01f * o1;
                float2 xi2 = *(const float2*)&XNI[(size_t)sn2 * BN + c];
                float2 xj2 = *(const float2*)&XNJ[(size_t)dn2 * BN + c];
                float p0 = acc[i][j][2] + xi2.x + xj2.x + b0;
                float p1 = acc[i][j][3] + xi2.y + xj2.y + b1;
                p0 = p0 > 0.f ? p0 : 0.01f * p0;
                p1 = p1 > 0.f ? p1 : 0.01f * p1;
                if (MODE == 1) {
                    *(uint32_t*)&Fhi[(size_t)gr1 * BN + c] = pk(o0, o1);
                    *(uint32_t*)&Flo[(size_t)gr1 * BN + c] = pk(o0 - bfe(o0), o1 - bfe(o1));
                    *(uint32_t*)&Fhi[(size_t)gr2 * BN + c] = pk(p0, p1);
                    *(uint32_t*)&Flo[(size_t)gr2 * BN + c] = pk(p0 - bfe(p0), p1 - bfe(p1));
                    float a0 = attn[c], a1 = attn[c + 1];
                    sc1 += o0 * a0 + o1 * a1;
                    sc2 += p0 * a0 + p1 * a1;
                } else {
                    *(float2*)&C[(size_t)gr1 * BN + c] = make_float2(o0, o1);
                    *(float2*)&C[(size_t)gr2 * BN + c] = make_float2(p0, p1);
                }
            }
            if (MODE == 1) {
                sc1 += __shfl_xor_sync(0xffffffffu, sc1, 1);
                sc1 += __shfl_xor_sync(0xffffffffu, sc1, 2);
                sc2 += __shfl_xor_sync(0xffffffffu, sc2, 1);
                sc2 += __shfl_xor_sync(0xffffffffu, sc2, 2);
                if (tig == 0) {
                    atomicAdd(&s_sc[lr1], sc1);
                    atomicAdd(&s_sc[lr2], sc2);
                }
            }
        }
        if (MODE == 1) {
            __syncthreads();
            if (tid < BM) score[row0 + tid] = s_sc[tid];
        }
    }
}

// ---------------- segment softmax over dst ----------------
__device__ __forceinline__ int enc_f(float f) {
    int i = __float_as_int(f);
    return i >= 0 ? i : (i ^ 0x7fffffff);
}
__device__ __forceinline__ float dec_f(int i) {
    return __int_as_float(i >= 0 ? i : (i ^ 0x7fffffff));
}

__global__ void seg_max(const float* __restrict__ score, const int* __restrict__ dst,
                        int* __restrict__ menc, int E) {
    int e = blockIdx.x * blockDim.x + threadIdx.x;
    if (e >= E) return;
    atomicMax(&menc[dst[e]], enc_f(score[e]));
}

__global__ void seg_expsum(const float* __restrict__ score, const int* __restrict__ dst,
                           const int* __restrict__ menc, float* __restrict__ ex,
                           float* __restrict__ ssum, int E) {
    int e = blockIdx.x * blockDim.x + threadIdx.x;
    if (e >= E) return;
    int d = dst[e];
    float ev = expf(score[e] - dec_f(menc[d]));
    ex[e] = ev;
    atomicAdd(&ssum[d], ev);
}

// ---------------- weighted aggregation ----------------
template<int DO>
__global__ void aggregate_k(const float* __restrict__ ex, const float* __restrict__ ssum,
                            const float* __restrict__ H, const int* __restrict__ src,
                            const int* __restrict__ dst, float* __restrict__ out, int E) {
    constexpr int L = DO / 4;
    long long gt = (long long)blockIdx.x * blockDim.x + threadIdx.x;
    int e = (int)(gt / L), l = (int)(gt % L);
    if (e >= E) return;
    int dn = dst[e];
    float a = ex[e] / ssum[dn];
    float4 h = *(const float4*)&H[(size_t)src[e] * DO + l * 4];
    float* p = &out[(size_t)dn * DO + l * 4];
    asm volatile("red.global.add.v4.f32 [%0], {%1,%2,%3,%4};"
                 :: "l"(p), "f"(h.x * a), "f"(h.y * a), "f"(h.z * a), "f"(h.w * a)
                 : "memory");
}

// ---------------- host ----------------
extern "C" void kernel_launch(void* const* d_in, const int* in_sizes, int n_in,
                              void* d_out, int out_size) {
    const float* x    = (const float*)d_in[0];
    const float* e    = (const float*)d_in[1];
    const int*   src  = (const int*)d_in[2];
    const int*   dst  = (const int*)d_in[3];

    const float* W_n1  = (const float*)d_in[4];
    const float* b_n1  = (const float*)d_in[5];
    const float* W_ni1 = (const float*)d_in[6];
    const float* W_nj1 = (const float*)d_in[7];
    const float* W_f1  = (const float*)d_in[8];
    const float* attn1 = (const float*)d_in[9];
    const float* bias1 = (const float*)d_in[10];

    const float* W_n2  = (const float*)d_in[11];
    const float* b_n2  = (const float*)d_in[12];
    const float* W_ni2 = (const float*)d_in[13];
    const float* W_nj2 = (const float*)d_in[14];
    const float* W_f2  = (const float*)d_in[15];
    const float* attn2 = (const float*)d_in[16];
    const float* bias2 = (const float*)d_in[17];

    const float* W_ni3 = (const float*)d_in[20];
    const float* W_nj3 = (const float*)d_in[21];
    const float* W_f3  = (const float*)d_in[22];
    const float* bias3 = (const float*)d_in[24];

    float* out = (float*)d_out;

    float *XNI, *XNJ, *H, *X2, *X3, *score, *ex, *ssum, *bn2, *bias2p, *attn2p;
    int* menc;
    __nv_bfloat16 *xP, *eP, *F1P, *F2P, *X2P, *X3P, *wts;
    cudaGetSymbolAddress((void**)&XNI, g_XNI);
    cudaGetSymbolAddress((void**)&XNJ, g_XNJ);
    cudaGetSymbolAddress((void**)&H,   g_H);
    cudaGetSymbolAddress((void**)&X2,  g_X2);
    cudaGetSymbolAddress((void**)&X3,  g_X3);
    cudaGetSymbolAddress((void**)&score, g_score);
    cudaGetSymbolAddress((void**)&ex,  g_ex);
    cudaGetSymbolAddress((void**)&ssum, g_ssum);
    cudaGetSymbolAddress((void**)&menc, g_menc);
    cudaGetSymbolAddress((void**)&bn2,  g_bn2);
    cudaGetSymbolAddress((void**)&bias2p, g_bias2);
    cudaGetSymbolAddress((void**)&attn2p, g_attn2);
    cudaGetSymbolAddress((void**)&xP,  g_xP);
    cudaGetSymbolAddress((void**)&eP,  g_eP);
    cudaGetSymbolAddress((void**)&F1P, g_F1P);
    cudaGetSymbolAddress((void**)&F2P, g_F2P);
    cudaGetSymbolAddress((void**)&X2P, g_X2P);
    cudaGetSymbolAddress((void**)&X3P, g_X3P);
    cudaGetSymbolAddress((void**)&wts, g_wts);

    const size_t xPN  = (size_t)NNP * 128;
    const size_t ePN  = (size_t)EE * 128;
    const size_t F2PN = (size_t)EE * 32;
    const size_t X3PN = (size_t)NNP * 32;
    const size_t WTN  = 4 * WL1 + 4 * WL2 + 3 * WL3;
    __nv_bfloat16 *wtH = wts, *wtL = wts + WTN;
    // weight plane offsets
    const int oWn1 = 0 * WL1, oWni1 = 1 * WL1, oWnj1 = 2 * WL1, oWf1 = 3 * WL1;
    const int base2 = 4 * WL1;
    const int oWn2 = base2, oWni2 = base2 + WL2, oWnj2 = base2 + 2 * WL2, oWf2 = base2 + 3 * WL2;
    const int base3 = base2 + 4 * WL2;
    const int oWni3 = base3, oWnj3 = base3 + WL3, oWf3 = base3 + 2 * WL3;

    const int Nn = NN, Ee = EE;
    const int nodeGrid = NNP / 128;          // 391
    const int edgeGrid = Ee / 128;           // 6250
    const int perThread = (Ee + 255) / 256;

    // ---- parameter prep (pads + weight plane conversion) ----
    VJobs vj;
    vj.j[0] = {b_n2,  bn2,    30, 32};
    vj.j[1] = {bias2, bias2p, 30, 32};
    vj.j[2] = {attn2, attn2p, 30, 32};
    pad_vec<<<dim3(1, 3), 32>>>(vj);

    WJobs wj;
    wj.j[0]  = {W_n1,  oWn1,  128, 128, 128, 128};
    wj.j[1]  = {W_ni1, oWni1, 128, 128, 128, 128};
    wj.j[2]  = {W_nj1, oWnj1, 128, 128, 128, 128};
    wj.j[3]  = {W_f1,  oWf1,  128, 128, 128, 128};
    wj.j[4]  = {W_n2,  oWn2,  128, 30, 128, 32};
    wj.j[5]  = {W_ni2, oWni2, 128, 30, 128, 32};
    wj.j[6]  = {W_nj2, oWnj2, 128, 30, 128, 32};
    wj.j[7]  = {W_f2,  oWf2,  128, 30, 128, 32};
    wj.j[8]  = {W_ni3, oWni3, 30, 64, 32, 64};
    wj.j[9]  = {W_nj3, oWnj3, 30, 64, 32, 64};
    wj.j[10] = {W_f3,  oWf3,  30, 64, 32, 64};
    conv_wt<<<dim3(64, 11), 256>>>(wj, wtH, wtL);

    // ---- input plane conversion ----
    conv_rows<<<(NNP * 16 + 255) / 256, 256>>>(x, xP, xP + xPN, Nn, 16, NNP);
    conv_rows<<<((int)(ePN / 8) + 255) / 256, 256>>>(e, eP, eP + ePN, Ee, 16, Ee);

    // ================= Layer 1 =================
    gemm_pl<128, 64, 32, 0><<<nodeGrid, 256>>>(xP, xP + xPN, wtH + oWni1, wtL + oWni1,
        XNI, nullptr, nullptr, nullptr, nullptr, nullptr, nullptr, nullptr, nullptr, nullptr, Nn, 128);
    gemm_pl<128, 64, 32, 0><<<nodeGrid, 256>>>(xP, xP + xPN, wtH + oWnj1, wtL + oWnj1,
        XNJ, nullptr, nullptr, nullptr, nullptr, nullptr, nullptr, nullptr, nullptr, nullptr, Nn, 128);
    gemm_pl<128, 64, 32, 0><<<nodeGrid, 256>>>(xP, xP + xPN, wtH + oWn1, wtL + oWn1,
        H, nullptr, nullptr, b_n1, nullptr, nullptr, nullptr, nullptr, nullptr, nullptr, Nn, 128);
    gemm_pl<128, 64, 32, 1><<<edgeGrid, 256>>>(eP, eP + ePN, wtH + oWf1, wtL + oWf1,
        nullptr, F1P, F1P + ePN, bias1, XNI, XNJ, src, dst, attn1, score, Ee, 128);

    cudaMemsetAsync(menc, 0x80, (size_t)Nn * sizeof(int), 0);
    cudaMemsetAsync(ssum, 0,    (size_t)Nn * sizeof(float), 0);
    cudaMemsetAsync(X2,   0,    (size_t)Nn * 128 * sizeof(float), 0);
    seg_max<<<perThread, 256>>>(score, dst, menc, Ee);
    seg_expsum<<<perThread, 256>>>(score, dst, menc, ex, ssum, Ee);
    aggregate_k<128><<<((long long)Ee * 32 + 255) / 256, 256>>>(ex, ssum, H, src, dst, X2, Ee);
    conv_rows<<<(NNP * 16 + 255) / 256, 256>>>(X2, X2P, X2P + xPN, Nn, 16, NNP);

    // ================= Layer 2 =================
    gemm_pl<32, 16, 32, 0><<<nodeGrid, 256>>>(X2P, X2P + xPN, wtH + oWni2, wtL + oWni2,
        XNI, nullptr, nullptr, nullptr, nullptr, nullptr, nullptr, nullptr, nullptr, nullptr, Nn, 128);
    gemm_pl<32, 16, 32, 0><<<nodeGrid, 256>>>(X2P, X2P + xPN, wtH + oWnj2, wtL + oWnj2,
        XNJ, nullptr, nullptr, nullptr, nullptr, nullptr, nullptr, nullptr, nullptr, nullptr, Nn, 128);
    gemm_pl<32, 16, 32, 0><<<nodeGrid, 256>>>(X2P, X2P + xPN, wtH + oWn2, wtL + oWn2,
        H, nullptr, nullptr, bn2, nullptr, nullptr, nullptr, nullptr, nullptr, nullptr, Nn, 128);
    gemm_pl<32, 16, 32, 1><<<edgeGrid, 256>>>(F1P, F1P + ePN, wtH + oWf2, wtL + oWf2,
        nullptr, F2P, F2P + F2PN, bias2p, XNI, XNJ, src, dst, attn2p, score, Ee, 128);

    cudaMemsetAsync(menc, 0x80, (size_t)Nn * sizeof(int), 0);
    cudaMemsetAsync(ssum, 0,    (size_t)Nn * sizeof(float), 0);
    cudaMemsetAsync(X3,   0,    (size_t)Nn * 32 * sizeof(float), 0);
    seg_max<<<perThread, 256>>>(score, dst, menc, Ee);
    seg_expsum<<<perThread, 256>>>(score, dst, menc, ex, ssum, Ee);
    aggregate_k<32><<<((long long)Ee * 8 + 255) / 256, 256>>>(ex, ssum, H, src, dst, X3, Ee);
    conv_rows<<<(NNP * 4 + 255) / 256, 256>>>(X3, X3P, X3P + X3PN, Nn, 4, NNP);

    // ================= Layer 3 (only f) =================
    gemm_pl<64, 32, 32, 0><<<nodeGrid, 256>>>(X3P, X3P + X3PN, wtH + oWni3, wtL + oWni3,
        XNI, nullptr, nullptr, nullptr, nullptr, nullptr, nullptr, nullptr, nullptr, nullptr, Nn, 32);
    gemm_pl<64, 32, 32, 0><<<nodeGrid, 256>>>(X3P, X3P + X3PN, wtH + oWnj3, wtL + oWnj3,
        XNJ, nullptr, nullptr, nullptr, nullptr, nullptr, nullptr, nullptr, nullptr, nullptr, Nn, 32);
    gemm_pl<64, 32, 32, 2><<<edgeGrid, 256>>>(F2P, F2P + F2PN, wtH + oWf3, wtL + oWf3,
        out, nullptr, nullptr, bias3, XNI, XNJ, src, dst, nullptr, nullptr, Ee, 32);

    (void)in_sizes; (void)n_in; (void)out_size;
}

// round 9
// speedup vs baseline: 1.6492x; 1.1604x over previous
#include <cuda_runtime.h>
#include <cuda_bf16.h>
#include <cstdint>
#include <cstddef>

#define NN 50000
#define EE 800000

// ---------------- static scratch ----------------
__device__ float g_XNI[(size_t)NN * 128];
__device__ float g_XNJ[(size_t)NN * 128];
__device__ float g_H  [(size_t)NN * 128];
__device__ float g_X2 [(size_t)NN * 128];
__device__ float g_X3 [(size_t)NN * 32];
__device__ float g_score[EE];
__device__ float g_ex[EE];
__device__ int   g_menc[NN];
__device__ float g_ssum[NN];
__device__ float g_bn2[32], g_bias2[32], g_attn2[32];

// bf16 hi/lo plane buffers (edge features between layers)
__device__ __nv_bfloat16 g_F1P[2][(size_t)EE * 128];
__device__ __nv_bfloat16 g_F2P[2][(size_t)EE * 32];
// weight plane arena: L1 4x[128][128], L2 4x[32][128], L3 3x[64][32]
#define WL1 (128 * 128)
#define WL2 (32 * 128)
#define WL3 (64 * 32)
__device__ __nv_bfloat16 g_wts[2][4 * WL1 + 4 * WL2 + 3 * WL3];

// ---------------- helpers ----------------
__device__ __forceinline__ uint32_t pk(float a, float b) {
    __nv_bfloat162 h = __floats2bfloat162_rn(a, b);
    return *(uint32_t*)&h;
}
__device__ __forceinline__ float bfe(float v) {
    return __bfloat162float(__float2bfloat16_rn(v));
}
__device__ __forceinline__ void mma16(float d[4], const uint32_t a[4], const uint32_t b[2]) {
    asm volatile(
        "mma.sync.aligned.m16n8k16.row.col.f32.bf16.bf16.f32 "
        "{%0,%1,%2,%3}, {%4,%5,%6,%7}, {%8,%9}, {%0,%1,%2,%3};\n"
        : "+f"(d[0]), "+f"(d[1]), "+f"(d[2]), "+f"(d[3])
        : "r"(a[0]), "r"(a[1]), "r"(a[2]), "r"(a[3]), "r"(b[0]), "r"(b[1]));
}
__device__ __forceinline__ void ldsm4(uint32_t r[4], uint32_t addr) {
    asm volatile("ldmatrix.sync.aligned.m8n8.x4.shared.b16 {%0,%1,%2,%3}, [%4];"
        : "=r"(r[0]), "=r"(r[1]), "=r"(r[2]), "=r"(r[3]) : "r"(addr));
}
__device__ __forceinline__ void ldsm2(uint32_t r[2], uint32_t addr) {
    asm volatile("ldmatrix.sync.aligned.m8n8.x2.shared.b16 {%0,%1}, [%2];"
        : "=r"(r[0]), "=r"(r[1]) : "r"(addr));
}
__device__ __forceinline__ void cpa16(uint32_t saddr, const void* g) {
    asm volatile("cp.async.ca.shared.global [%0], [%1], 16;" :: "r"(saddr), "l"(g));
}
__device__ __forceinline__ void cp_commit() {
    asm volatile("cp.async.commit_group;");
}
template<int N>
__device__ __forceinline__ void cp_wait() {
    asm volatile("cp.async.wait_group %0;" :: "n"(N) : "memory");
}

// ---------------- weight conversion: f32 [K][N] -> transposed planes [Np][Kp] ----------------
struct WJob { const float* w; int off, K, N, Kp, Np; };
struct WJobs { WJob j[11]; };
__global__ void conv_wt(WJobs js, __nv_bfloat16* hiB, __nv_bfloat16* loB) {
    WJob jb = js.j[blockIdx.y];
    int i = blockIdx.x * blockDim.x + threadIdx.x;
    if (i >= jb.Np * jb.Kp) return;
    int n = i / jb.Kp, k = i % jb.Kp;
    float v = (n < jb.N && k < jb.K) ? jb.w[k * jb.N + n] : 0.0f;
    __nv_bfloat16 h = __float2bfloat16_rn(v);
    hiB[jb.off + i] = h;
    loB[jb.off + i] = __float2bfloat16_rn(v - __bfloat162float(h));
}

// pad small f32 vectors (30 -> 32)
struct VJob { const float* in; float* out; int C, nC; };
struct VJobs { VJob j[3]; };
__global__ void pad_vec(VJobs js) {
    VJob p = js.j[blockIdx.y];
    int i = threadIdx.x;
    if (i < p.nC) p.out[i] = (i < p.C) ? p.in[i] : 0.0f;
}

// ---------------- plane GEMM: double-buffered cp.async + ldmatrix + bf16x3 ----------------
// AF32=1: A is f32 row-major [M][K] (converted to hi/lo in-kernel, reg-staged).
// AF32=0: A is bf16 hi/lo planes (Apv hi, Apv2 lo), M must be multiple of 128.
// MODE 0: C(f32, stride BN) = A@B (+bias), row guard on stores
// MODE 1: F planes = split(leaky(A@B + XNI[src] + XNJ[dst] + bias)); score
// MODE 2: C(f32) = leaky(...) (no score). MODE>=1: M % 128 == 0.
template<int BN, int WM, int WN, int MODE, int AF32>
__global__ __launch_bounds__(256, 2) void gemm_pl(
    const void* __restrict__ Apv, const void* __restrict__ Apv2,
    const __nv_bfloat16* __restrict__ Bhi, const __nv_bfloat16* __restrict__ Blo,
    float* __restrict__ C, __nv_bfloat16* __restrict__ Fhi, __nv_bfloat16* __restrict__ Flo,
    const float* __restrict__ bias,
    const float* __restrict__ XNI, const float* __restrict__ XNJ,
    const int* __restrict__ src, const int* __restrict__ dst,
    const float* __restrict__ attn, float* __restrict__ score,
    int M, int K)
{
    constexpr int BM = 128;
    constexpr int MT = WM / 16, NT = WN / 8;
    constexpr int WARPS_N = BN / WN;
    static_assert((BM / WM) * (BN / WN) == 8, "need 8 warps");

    // [stage][plane][row][24] — 48B row stride, conflict-free ldmatrix
    __shared__ __align__(16) __nv_bfloat16 sA[2][2][BM][24];
    __shared__ __align__(16) __nv_bfloat16 sB[2][2][BN][24];
    __shared__ float s_sc[BM];

    const int tid  = threadIdx.x;
    const int warp = tid >> 5, lane = tid & 31;
    const int gid  = lane >> 2, tig = lane & 3;
    const int wm   = warp / WARPS_N, wn = warp % WARPS_N;
    const int rowW = wm * WM, colW = wn * WN;
    const int row0 = blockIdx.x * BM;

    const uint32_t aBase = (uint32_t)__cvta_generic_to_shared(&sA[0][0][0][0]);
    const uint32_t bBase = (uint32_t)__cvta_generic_to_shared(&sB[0][0][0][0]);

    const float* Af = (const float*)Apv;
    const __nv_bfloat16* Ahi = (const __nv_bfloat16*)Apv;
    const __nv_bfloat16* Alo = (const __nv_bfloat16*)Apv2;

    if (MODE == 1 && tid < BM) s_sc[tid] = 0.0f;

    float acc[MT][NT][4];
    #pragma unroll
    for (int i = 0; i < MT; i++)
        #pragma unroll
        for (int j = 0; j < NT; j++)
            #pragma unroll
            for (int t = 0; t < 4; t++) acc[i][j][t] = 0.0f;

    const int lrA = lane & 15;
    const int kofA = ((lane >> 4) & 1) * 16;
    const int lrB = lane & 7;
    const int kofB = ((lane >> 3) & 1) * 16;

    const int T = K >> 4;

    // A f32 reg staging (AF32 path): thread -> (row, 8-col half)
    const int arow = tid >> 1, ahalf = tid & 1;
    float areg[8];

    auto loadAf32 = [&](int t) {
        int gr = row0 + arow;
        if (gr < M) {
            const float* p = &Af[(size_t)gr * K + t * 16 + ahalf * 8];
            float4 q0 = *(const float4*)p;
            float4 q1 = *(const float4*)(p + 4);
            areg[0] = q0.x; areg[1] = q0.y; areg[2] = q0.z; areg[3] = q0.w;
            areg[4] = q1.x; areg[5] = q1.y; areg[6] = q1.z; areg[7] = q1.w;
        } else {
            #pragma unroll
            for (int t2 = 0; t2 < 8; t2++) areg[t2] = 0.0f;
        }
    };
    auto stsA = [&](int s) {
        __nv_bfloat16 h[8], l[8];
        #pragma unroll
        for (int t2 = 0; t2 < 8; t2++) {
            h[t2] = __float2bfloat16_rn(areg[t2]);
            l[t2] = __float2bfloat16_rn(areg[t2] - __bfloat162float(h[t2]));
        }
        *(uint4*)&sA[s][0][arow][ahalf * 8] = *(uint4*)h;
        *(uint4*)&sA[s][1][arow][ahalf * 8] = *(uint4*)l;
    };
    auto issueB = [&](int t, int s) {
        #pragma unroll 1
        for (int c = tid; c < BN * 4; c += 256) {
            int half = c & 1, pl = (c >> 1) & 1, n = c >> 2;
            const __nv_bfloat16* g = (pl ? Blo : Bhi) + (size_t)n * K + t * 16 + half * 8;
            cpa16(bBase + (uint32_t)(((s * 2 + pl) * BN + n) * 48 + half * 16), g);
        }
    };
    auto issueApl = [&](int t, int s) {
        #pragma unroll 1
        for (int c = tid; c < BM * 4; c += 256) {
            int half = c & 1, pl = (c >> 1) & 1, r = c >> 2;
            const __nv_bfloat16* g = (pl ? Alo : Ahi) + (size_t)(row0 + r) * K + t * 16 + half * 8;
            cpa16(aBase + (uint32_t)(((s * 2 + pl) * BM + r) * 48 + half * 16), g);
        }
    };
    auto mmaStage = [&](int s) {
        uint32_t ah[MT][4], al[MT][4];
        uint32_t aOff = aBase + (uint32_t)(s * 2 * BM * 48);
        uint32_t bOff = bBase + (uint32_t)(s * 2 * BN * 48);
        #pragma unroll
        for (int i = 0; i < MT; i++) {
            uint32_t ra = aOff + (uint32_t)((rowW + i * 16 + lrA) * 48) + kofA;
            ldsm4(ah[i], ra);
            ldsm4(al[i], ra + (uint32_t)(BM * 48));
        }
        #pragma unroll
        for (int j = 0; j < NT; j++) {
            uint32_t rb = bOff + (uint32_t)((colW + j * 8 + lrB) * 48) + kofB;
            uint32_t bh[2], bl[2];
            ldsm2(bh, rb);
            ldsm2(bl, rb + (uint32_t)(BN * 48));
            #pragma unroll
            for (int i = 0; i < MT; i++) {
                mma16(acc[i][j], ah[i], bh);
                mma16(acc[i][j], ah[i], bl);
                mma16(acc[i][j], al[i], bh);
            }
        }
    };

    if (AF32) {
        loadAf32(0);
        issueB(0, 0); cp_commit();
        for (int t = 0; t < T; t++) {
            int s = t & 1;
            __syncthreads();                 // prior readers of buffers s are done
            stsA(s);
            if (t + 1 < T) {
                issueB(t + 1, 1 - s); cp_commit();
                loadAf32(t + 1);
                cp_wait<1>();
            } else {
                cp_wait<0>();
            }
            __syncthreads();                 // STS + cp.async arrivals visible
            mmaStage(s);
        }
    } else {
        issueApl(0, 0); issueB(0, 0); cp_commit();
        for (int t = 0; t < T; t++) {
            int s = t & 1;
            if (t + 1 < T) {
                issueApl(t + 1, 1 - s); issueB(t + 1, 1 - s); cp_commit();
                cp_wait<1>();
            } else {
                cp_wait<0>();
            }
            __syncthreads();
            mmaStage(s);
            __syncthreads();                 // readers done before next overwrite
        }
    }

    // ---------------- epilogue ----------------
    if (MODE == 0) {
        #pragma unroll
        for (int i = 0; i < MT; i++) {
            int gr1 = row0 + rowW + i * 16 + gid;
            int gr2 = gr1 + 8;
            #pragma unroll
            for (int j = 0; j < NT; j++) {
                int c = colW + j * 8 + 2 * tig;
                float b0 = bias ? bias[c] : 0.0f;
                float b1 = bias ? bias[c + 1] : 0.0f;
                if (gr1 < M)
                    *(float2*)&C[(size_t)gr1 * BN + c] =
                        make_float2(acc[i][j][0] + b0, acc[i][j][1] + b1);
                if (gr2 < M)
                    *(float2*)&C[(size_t)gr2 * BN + c] =
                        make_float2(acc[i][j][2] + b0, acc[i][j][3] + b1);
            }
        }
    } else {
        #pragma unroll
        for (int i = 0; i < MT; i++) {
            int lr1 = rowW + i * 16 + gid, lr2 = lr1 + 8;
            int gr1 = row0 + lr1, gr2 = row0 + lr2;
            int sn1 = src[gr1], dn1 = dst[gr1];
            int sn2 = src[gr2], dn2 = dst[gr2];
            float sc1 = 0.0f, sc2 = 0.0f;
            #pragma unroll
            for (int j = 0; j < NT; j++) {
                int c = colW + j * 8 + 2 * tig;
                float b0 = bias[c], b1 = bias[c + 1];
                float2 xi1 = *(const float2*)&XNI[(size_t)sn1 * BN + c];
                float2 xj1 = *(const float2*)&XNJ[(size_t)dn1 * BN + c];
                float o0 = acc[i][j][0] + xi1.x + xj1.x + b0;
                float o1 = acc[i][j][1] + xi1.y + xj1.y + b1;
                o0 = o0 > 0.f ? o0 : 0.01f * o0;
                o1 = o1 > 0.f ? o1 : 0.01f * o1;
                float2 xi2 = *(const float2*)&XNI[(size_t)sn2 * BN + c];
                float2 xj2 = *(const float2*)&XNJ[(size_t)dn2 * BN + c];
                float p0 = acc[i][j][2] + xi2.x + xj2.x + b0;
                float p1 = acc[i][j][3] + xi2.y + xj2.y + b1;
                p0 = p0 > 0.f ? p0 : 0.01f * p0;
                p1 = p1 > 0.f ? p1 : 0.01f * p1;
                if (MODE == 1) {
                    *(uint32_t*)&Fhi[(size_t)gr1 * BN + c] = pk(o0, o1);
                    *(uint32_t*)&Flo[(size_t)gr1 * BN + c] = pk(o0 - bfe(o0), o1 - bfe(o1));
                    *(uint32_t*)&Fhi[(size_t)gr2 * BN + c] = pk(p0, p1);
                    *(uint32_t*)&Flo[(size_t)gr2 * BN + c] = pk(p0 - bfe(p0), p1 - bfe(p1));
                    float a0 = attn[c], a1 = attn[c + 1];
                    sc1 += o0 * a0 + o1 * a1;
                    sc2 += p0 * a0 + p1 * a1;
                } else {
                    *(float2*)&C[(size_t)gr1 * BN + c] = make_float2(o0, o1);
                    *(float2*)&C[(size_t)gr2 * BN + c] = make_float2(p0, p1);
                }
            }
            if (MODE == 1) {
                sc1 += __shfl_xor_sync(0xffffffffu, sc1, 1);
                sc1 += __shfl_xor_sync(0xffffffffu, sc1, 2);
                sc2 += __shfl_xor_sync(0xffffffffu, sc2, 1);
                sc2 += __shfl_xor_sync(0xffffffffu, sc2, 2);
                if (tig == 0) {
                    atomicAdd(&s_sc[lr1], sc1);
                    atomicAdd(&s_sc[lr2], sc2);
                }
            }
        }
        if (MODE == 1) {
            __syncthreads();
            if (tid < BM) score[row0 + tid] = s_sc[tid];
        }
    }
}

// ---------------- segment softmax over dst ----------------
__device__ __forceinline__ int enc_f(float f) {
    int i = __float_as_int(f);
    return i >= 0 ? i : (i ^ 0x7fffffff);
}
__device__ __forceinline__ float dec_f(int i) {
    return __int_as_float(i >= 0 ? i : (i ^ 0x7fffffff));
}

__global__ void seg_max(const float* __restrict__ score, const int* __restrict__ dst,
                        int* __restrict__ menc, int E) {
    int e = blockIdx.x * blockDim.x + threadIdx.x;
    if (e >= E) return;
    atomicMax(&menc[dst[e]], enc_f(score[e]));
}

__global__ void seg_expsum(const float* __restrict__ score, const int* __restrict__ dst,
                           const int* __restrict__ menc, float* __restrict__ ex,
                           float* __restrict__ ssum, int E) {
    int e = blockIdx.x * blockDim.x + threadIdx.x;
    if (e >= E) return;
    int d = dst[e];
    float ev = expf(score[e] - dec_f(menc[d]));
    ex[e] = ev;
    atomicAdd(&ssum[d], ev);
}

// ---------------- weighted aggregation ----------------
template<int DO>
__global__ void aggregate_k(const float* __restrict__ ex, const float* __restrict__ ssum,
                            const float* __restrict__ H, const int* __restrict__ src,
                            const int* __restrict__ dst, float* __restrict__ out, int E) {
    constexpr int L = DO / 4;
    long long gt = (long long)blockIdx.x * blockDim.x + threadIdx.x;
    int e = (int)(gt / L), l = (int)(gt % L);
    if (e >= E) return;
    int dn = dst[e];
    float a = ex[e] / ssum[dn];
    float4 h = *(const float4*)&H[(size_t)src[e] * DO + l * 4];
    float* p = &out[(size_t)dn * DO + l * 4];
    asm volatile("red.global.add.v4.f32 [%0], {%1,%2,%3,%4};"
                 :: "l"(p), "f"(h.x * a), "f"(h.y * a), "f"(h.z * a), "f"(h.w * a)
                 : "memory");
}

// ---------------- host ----------------
extern "C" void kernel_launch(void* const* d_in, const int* in_sizes, int n_in,
                              void* d_out, int out_size) {
    const float* x    = (const float*)d_in[0];
    const float* e    = (const float*)d_in[1];
    const int*   src  = (const int*)d_in[2];
    const int*   dst  = (const int*)d_in[3];

    const float* W_n1  = (const float*)d_in[4];
    const float* b_n1  = (const float*)d_in[5];
    const float* W_ni1 = (const float*)d_in[6];
    const float* W_nj1 = (const float*)d_in[7];
    const float* W_f1  = (const float*)d_in[8];
    const float* attn1 = (const float*)d_in[9];
    const float* bias1 = (const float*)d_in[10];

    const float* W_n2  = (const float*)d_in[11];
    const float* b_n2  = (const float*)d_in[12];
    const float* W_ni2 = (const float*)d_in[13];
    const float* W_nj2 = (const float*)d_in[14];
    const float* W_f2  = (const float*)d_in[15];
    const float* attn2 = (const float*)d_in[16];
    const float* bias2 = (const float*)d_in[17];

    const float* W_ni3 = (const float*)d_in[20];
    const float* W_nj3 = (const float*)d_in[21];
    const float* W_f3  = (const float*)d_in[22];
    const float* bias3 = (const float*)d_in[24];

    float* out = (float*)d_out;

    float *XNI, *XNJ, *H, *X2, *X3, *score, *ex, *ssum, *bn2, *bias2p, *attn2p;
    int* menc;
    __nv_bfloat16 *F1P, *F2P, *wts;
    cudaGetSymbolAddress((void**)&XNI, g_XNI);
    cudaGetSymbolAddress((void**)&XNJ, g_XNJ);
    cudaGetSymbolAddress((void**)&H,   g_H);
    cudaGetSymbolAddress((void**)&X2,  g_X2);
    cudaGetSymbolAddress((void**)&X3,  g_X3);
    cudaGetSymbolAddress((void**)&score, g_score);
    cudaGetSymbolAddress((void**)&ex,  g_ex);
    cudaGetSymbolAddress((void**)&ssum, g_ssum);
    cudaGetSymbolAddress((void**)&menc, g_menc);
    cudaGetSymbolAddress((void**)&bn2,  g_bn2);
    cudaGetSymbolAddress((void**)&bias2p, g_bias2);
    cudaGetSymbolAddress((void**)&attn2p, g_attn2);
    cudaGetSymbolAddress((void**)&F1P, g_F1P);
    cudaGetSymbolAddress((void**)&F2P, g_F2P);
    cudaGetSymbolAddress((void**)&wts, g_wts);

    const size_t ePN  = (size_t)EE * 128;
    const size_t F2PN = (size_t)EE * 32;
    const size_t WTN  = 4 * WL1 + 4 * WL2 + 3 * WL3;
    __nv_bfloat16 *wtH = wts, *wtL = wts + WTN;
    const int oWn1 = 0 * WL1, oWni1 = 1 * WL1, oWnj1 = 2 * WL1, oWf1 = 3 * WL1;
    const int base2 = 4 * WL1;
    const int oWn2 = base2, oWni2 = base2 + WL2, oWnj2 = base2 + 2 * WL2, oWf2 = base2 + 3 * WL2;
    const int base3 = base2 + 4 * WL2;
    const int oWni3 = base3, oWnj3 = base3 + WL3, oWf3 = base3 + 2 * WL3;

    const int Nn = NN, Ee = EE;
    const int nodeGrid = (Nn + 127) / 128;   // 391
    const int edgeGrid = Ee / 128;           // 6250
    const int perThread = (Ee + 255) / 256;

    // ---- parameter prep ----
    VJobs vj;
    vj.j[0] = {b_n2,  bn2,    30, 32};
    vj.j[1] = {bias2, bias2p, 30, 32};
    vj.j[2] = {attn2, attn2p, 30, 32};
    pad_vec<<<dim3(1, 3), 32>>>(vj);

    WJobs wj;
    wj.j[0]  = {W_n1,  oWn1,  128, 128, 128, 128};
    wj.j[1]  = {W_ni1, oWni1, 128, 128, 128, 128};
    wj.j[2]  = {W_nj1, oWnj1, 128, 128, 128, 128};
    wj.j[3]  = {W_f1,  oWf1,  128, 128, 128, 128};
    wj.j[4]  = {W_n2,  oWn2,  128, 30, 128, 32};
    wj.j[5]  = {W_ni2, oWni2, 128, 30, 128, 32};
    wj.j[6]  = {W_nj2, oWnj2, 128, 30, 128, 32};
    wj.j[7]  = {W_f2,  oWf2,  128, 30, 128, 32};
    wj.j[8]  = {W_ni3, oWni3, 30, 64, 32, 64};
    wj.j[9]  = {W_nj3, oWnj3, 30, 64, 32, 64};
    wj.j[10] = {W_f3,  oWf3,  30, 64, 32, 64};
    conv_wt<<<dim3(64, 11), 256>>>(wj, wtH, wtL);

    // ================= Layer 1 (A = f32 inputs, converted in-kernel) =================
    gemm_pl<128, 64, 32, 0, 1><<<nodeGrid, 256>>>(x, nullptr, wtH + oWni1, wtL + oWni1,
        XNI, nullptr, nullptr, nullptr, nullptr, nullptr, nullptr, nullptr, nullptr, nullptr, Nn, 128);
    gemm_pl<128, 64, 32, 0, 1><<<nodeGrid, 256>>>(x, nullptr, wtH + oWnj1, wtL + oWnj1,
        XNJ, nullptr, nullptr, nullptr, nullptr, nullptr, nullptr, nullptr, nullptr, nullptr, Nn, 128);
    gemm_pl<128, 64, 32, 0, 1><<<nodeGrid, 256>>>(x, nullptr, wtH + oWn1, wtL + oWn1,
        H, nullptr, nullptr, b_n1, nullptr, nullptr, nullptr, nullptr, nullptr, nullptr, Nn, 128);
    gemm_pl<128, 64, 32, 1, 1><<<edgeGrid, 256>>>(e, nullptr, wtH + oWf1, wtL + oWf1,
        nullptr, F1P, F1P + ePN, bias1, XNI, XNJ, src, dst, attn1, score, Ee, 128);

    cudaMemsetAsync(menc, 0x80, (size_t)Nn * sizeof(int), 0);
    cudaMemsetAsync(ssum, 0,    (size_t)Nn * sizeof(float), 0);
    cudaMemsetAsync(X2,   0,    (size_t)Nn * 128 * sizeof(float), 0);
    seg_max<<<perThread, 256>>>(score, dst, menc, Ee);
    seg_expsum<<<perThread, 256>>>(score, dst, menc, ex, ssum, Ee);
    aggregate_k<128><<<((long long)Ee * 32 + 255) / 256, 256>>>(ex, ssum, H, src, dst, X2, Ee);

    // ================= Layer 2 =================
    gemm_pl<32, 16, 32, 0, 1><<<nodeGrid, 256>>>(X2, nullptr, wtH + oWni2, wtL + oWni2,
        XNI, nullptr, nullptr, nullptr, nullptr, nullptr, nullptr, nullptr, nullptr, nullptr, Nn, 128);
    gemm_pl<32, 16, 32, 0, 1><<<nodeGrid, 256>>>(X2, nullptr, wtH + oWnj2, wtL + oWnj2,
        XNJ, nullptr, nullptr, nullptr, nullptr, nullptr, nullptr, nullptr, nullptr, nullptr, Nn, 128);
    gemm_pl<32, 16, 32, 0, 1><<<nodeGrid, 256>>>(X2, nullptr, wtH + oWn2, wtL + oWn2,
        H, nullptr, nullptr, bn2, nullptr, nullptr, nullptr, nullptr, nullptr, nullptr, Nn, 128);
    gemm_pl<32, 16, 32, 1, 0><<<edgeGrid, 256>>>(F1P, F1P + ePN, wtH + oWf2, wtL + oWf2,
        nullptr, F2P, F2P + F2PN, bias2p, XNI, XNJ, src, dst, attn2p, score, Ee, 128);

    cudaMemsetAsync(menc, 0x80, (size_t)Nn * sizeof(int), 0);
    cudaMemsetAsync(ssum, 0,    (size_t)Nn * sizeof(float), 0);
    cudaMemsetAsync(X3,   0,    (size_t)Nn * 32 * sizeof(float), 0);
    seg_max<<<perThread, 256>>>(score, dst, menc, Ee);
    seg_expsum<<<perThread, 256>>>(score, dst, menc, ex, ssum, Ee);
    aggregate_k<32><<<((long long)Ee * 8 + 255) / 256, 256>>>(ex, ssum, H, src, dst, X3, Ee);

    // ================= Layer 3 (only f) =================
    gemm_pl<64, 32, 32, 0, 1><<<nodeGrid, 256>>>(X3, nullptr, wtH + oWni3, wtL + oWni3,
        XNI, nullptr, nullptr, nullptr, nullptr, nullptr, nullptr, nullptr, nullptr, nullptr, Nn, 32);
    gemm_pl<64, 32, 32, 0, 1><<<nodeGrid, 256>>>(X3, nullptr, wtH + oWnj3, wtL + oWnj3,
        XNJ, nullptr, nullptr, nullptr, nullptr, nullptr, nullptr, nullptr, nullptr, nullptr, Nn, 32);
    gemm_pl<64, 32, 32, 2, 0><<<edgeGrid, 256>>>(F2P, F2P + F2PN, wtH + oWf3, wtL + oWf3,
        out, nullptr, nullptr, bias3, XNI, XNJ, src, dst, nullptr, nullptr, Ee, 32);

    (void)in_sizes; (void)n_in; (void)out_size;
}

// round 10
// speedup vs baseline: 1.7743x; 1.0758x over previous
#include <cuda_runtime.h>
#include <cuda_bf16.h>
#include <cstdint>
#include <cstddef>

#define NN 50000
#define EE 800000

// ---------------- static scratch ----------------
__device__ float g_XNI[(size_t)NN * 128];
__device__ float g_XNJ[(size_t)NN * 128];
__device__ float g_H  [(size_t)NN * 128];
__device__ float g_X2 [(size_t)NN * 128];
__device__ float g_X3 [(size_t)NN * 32];
__device__ float g_score[EE];
__device__ float g_ex[EE];
__device__ int   g_menc[NN];
__device__ float g_ssum[NN];
__device__ float g_bn2[32], g_bias2[32], g_attn2[32];

__device__ __nv_bfloat16 g_F1P[2][(size_t)EE * 128];
__device__ __nv_bfloat16 g_F2P[2][(size_t)EE * 32];
#define WL1 (128 * 128)
#define WL2 (32 * 128)
#define WL3 (64 * 32)
__device__ __nv_bfloat16 g_wts[2][4 * WL1 + 4 * WL2 + 3 * WL3];

// ---------------- helpers ----------------
__device__ __forceinline__ uint32_t pk(float a, float b) {
    __nv_bfloat162 h = __floats2bfloat162_rn(a, b);
    return *(uint32_t*)&h;
}
__device__ __forceinline__ float bfe(float v) {
    return __bfloat162float(__float2bfloat16_rn(v));
}
__device__ __forceinline__ void mma16(float d[4], const uint32_t a[4], const uint32_t b[2]) {
    asm volatile(
        "mma.sync.aligned.m16n8k16.row.col.f32.bf16.bf16.f32 "
        "{%0,%1,%2,%3}, {%4,%5,%6,%7}, {%8,%9}, {%0,%1,%2,%3};\n"
        : "+f"(d[0]), "+f"(d[1]), "+f"(d[2]), "+f"(d[3])
        : "r"(a[0]), "r"(a[1]), "r"(a[2]), "r"(a[3]), "r"(b[0]), "r"(b[1]));
}
__device__ __forceinline__ void ldsm4(uint32_t r[4], uint32_t addr) {
    asm volatile("ldmatrix.sync.aligned.m8n8.x4.shared.b16 {%0,%1,%2,%3}, [%4];"
        : "=r"(r[0]), "=r"(r[1]), "=r"(r[2]), "=r"(r[3]) : "r"(addr));
}
__device__ __forceinline__ void ldsm2(uint32_t r[2], uint32_t addr) {
    asm volatile("ldmatrix.sync.aligned.m8n8.x2.shared.b16 {%0,%1}, [%2];"
        : "=r"(r[0]), "=r"(r[1]) : "r"(addr));
}
__device__ __forceinline__ void cpa16(uint32_t saddr, const void* g) {
    asm volatile("cp.async.ca.shared.global [%0], [%1], 16;" :: "r"(saddr), "l"(g));
}
__device__ __forceinline__ void cp_commit() {
    asm volatile("cp.async.commit_group;");
}
template<int N>
__device__ __forceinline__ void cp_wait() {
    asm volatile("cp.async.wait_group %0;" :: "n"(N) : "memory");
}

// ---------------- weight conversion: f32 [K][N] -> transposed planes [Np][Kp] ----------------
struct WJob { const float* w; int off, K, N, Kp, Np; };
struct WJobs { WJob j[11]; };
__global__ void conv_wt(WJobs js, __nv_bfloat16* hiB, __nv_bfloat16* loB) {
    WJob jb = js.j[blockIdx.y];
    int i = blockIdx.x * blockDim.x + threadIdx.x;
    if (i >= jb.Np * jb.Kp) return;
    int n = i / jb.Kp, k = i % jb.Kp;
    float v = (n < jb.N && k < jb.K) ? jb.w[k * jb.N + n] : 0.0f;
    __nv_bfloat16 h = __float2bfloat16_rn(v);
    hiB[jb.off + i] = h;
    loB[jb.off + i] = __float2bfloat16_rn(v - __bfloat162float(h));
}

struct VJob { const float* in; float* out; int C, nC; };
struct VJobs { VJob j[3]; };
__global__ void pad_vec(VJobs js) {
    VJob p = js.j[blockIdx.y];
    int i = threadIdx.x;
    if (i < p.nC) p.out[i] = (i < p.C) ? p.in[i] : 0.0f;
}

// ---------------- GEMM: B fully smem-resident, 1 sync per stage, bf16x3 ----------------
// AF32=1: A is f32 [M][K], converted in-kernel (reg staged, double-buffered STS).
// AF32=0: A is bf16 hi/lo planes, 3-stage cp.async ring. M % 128 == 0 for MODE>=1.
// MODE 0: C = A@B (+bias). MODE 1: F planes + score. MODE 2: C = leaky(...).
template<int BN, int KT, int WM, int WN, int MODE, int AF32>
__global__ __launch_bounds__(256, 2) void gemm_pl(
    const void* __restrict__ Apv, const void* __restrict__ Apv2,
    const __nv_bfloat16* __restrict__ Bhi, const __nv_bfloat16* __restrict__ Blo,
    float* __restrict__ C, __nv_bfloat16* __restrict__ Fhi, __nv_bfloat16* __restrict__ Flo,
    const float* __restrict__ bias,
    const float* __restrict__ XNI, const float* __restrict__ XNJ,
    const int* __restrict__ src, const int* __restrict__ dst,
    const float* __restrict__ attn, float* __restrict__ score, int M)
{
    constexpr int BM = 128, T = KT / 16, NS = AF32 ? 2 : 3;
    constexpr int BS = KT * 2 + 16;            // B row stride in bytes (conflict-free)
    constexpr int MT = WM / 16, NT = WN / 8;
    constexpr int WARPS_N = BN / WN;
    static_assert((BM / WM) * (BN / WN) == 8, "need 8 warps");

    extern __shared__ __align__(16) char dynsm[];
    char* sBp = dynsm + NS * 2 * BM * 48;
    float* s_sc = (float*)(sBp + 2 * BN * BS);

    const int tid  = threadIdx.x;
    const int warp = tid >> 5, lane = tid & 31;
    const int gid  = lane >> 2, tig = lane & 3;
    const int wm   = warp / WARPS_N, wn = warp % WARPS_N;
    const int rowW = wm * WM, colW = wn * WN;
    const int row0 = blockIdx.x * BM;

    const uint32_t aBase = (uint32_t)__cvta_generic_to_shared(dynsm);
    const uint32_t bBase = (uint32_t)__cvta_generic_to_shared(sBp);

    const float* Af = (const float*)Apv;
    const __nv_bfloat16* Ahi = (const __nv_bfloat16*)Apv;
    const __nv_bfloat16* Alo = (const __nv_bfloat16*)Apv2;

    if (MODE == 1 && tid < BM) s_sc[tid] = 0.0f;

    float acc[MT][NT][4];
    #pragma unroll
    for (int i = 0; i < MT; i++)
        #pragma unroll
        for (int j = 0; j < NT; j++)
            #pragma unroll
            for (int t = 0; t < 4; t++) acc[i][j][t] = 0.0f;

    const int lrA = lane & 15;
    const int kofA = ((lane >> 4) & 1) * 16;
    const int lrB = lane & 7;
    const int kofB = ((lane >> 3) & 1) * 16;

    const int arow = tid >> 1, ahalf = tid & 1;
    float areg[8];

    auto issueB = [&]() {
        constexpr int CH = KT / 8;             // 16B chunks per row
        #pragma unroll
        for (int c = tid; c < 2 * BN * CH; c += 256) {
            int pl = c / (BN * CH);
            int rem = c - pl * BN * CH;
            int n = rem / CH, ch = rem - n * CH;
            const __nv_bfloat16* g = (pl ? Blo : Bhi) + (size_t)n * KT + ch * 8;
            cpa16(bBase + (uint32_t)((pl * BN + n) * BS + ch * 16), g);
        }
    };
    auto loadAf32 = [&](int t) {
        int gr = row0 + arow;
        if (gr < M) {
            const float* p = &Af[(size_t)gr * KT + t * 16 + ahalf * 8];
            float4 q0 = *(const float4*)p;
            float4 q1 = *(const float4*)(p + 4);
            areg[0] = q0.x; areg[1] = q0.y; areg[2] = q0.z; areg[3] = q0.w;
            areg[4] = q1.x; areg[5] = q1.y; areg[6] = q1.z; areg[7] = q1.w;
        } else {
            #pragma unroll
            for (int u = 0; u < 8; u++) areg[u] = 0.0f;
        }
    };
    auto stsA = [&](int s) {
        __nv_bfloat16 h[8], l[8];
        #pragma unroll
        for (int u = 0; u < 8; u++) {
            h[u] = __float2bfloat16_rn(areg[u]);
            l[u] = __float2bfloat16_rn(areg[u] - __bfloat162float(h[u]));
        }
        __nv_bfloat16* base = (__nv_bfloat16*)dynsm;
        *(uint4*)&base[((s * 2 + 0) * BM + arow) * 24 + ahalf * 8] = *(uint4*)h;
        *(uint4*)&base[((s * 2 + 1) * BM + arow) * 24 + ahalf * 8] = *(uint4*)l;
    };
    auto issueApl = [&](int t, int s) {
        #pragma unroll
        for (int c = tid; c < BM * 4; c += 256) {
            int half = c & 1, pl = (c >> 1) & 1, r = c >> 2;
            const __nv_bfloat16* g = (pl ? Alo : Ahi) + (size_t)(row0 + r) * KT + t * 16 + half * 8;
            cpa16(aBase + (uint32_t)(((s * 2 + pl) * BM + r) * 48 + half * 16), g);
        }
    };
    auto mmaStage = [&](int s, int t) {
        uint32_t ah[MT][4], al[MT][4];
        uint32_t aOff = aBase + (uint32_t)(s * 2 * BM * 48);
        #pragma unroll
        for (int i = 0; i < MT; i++) {
            uint32_t ra = aOff + (uint32_t)((rowW + i * 16 + lrA) * 48) + kofA;
            ldsm4(ah[i], ra);
            ldsm4(al[i], ra + (uint32_t)(BM * 48));
        }
        #pragma unroll
        for (int j = 0; j < NT; j++) {
            uint32_t rb = bBase + (uint32_t)((colW + j * 8 + lrB) * BS) + (uint32_t)(t * 32) + kofB;
            uint32_t bh[2], bl[2];
            ldsm2(bh, rb);
            ldsm2(bl, rb + (uint32_t)(BN * BS));
            #pragma unroll
            for (int i = 0; i < MT; i++) {
                mma16(acc[i][j], ah[i], bh);
                mma16(acc[i][j], ah[i], bl);
                mma16(acc[i][j], al[i], bh);
            }
        }
    };

    if (AF32) {
        loadAf32(0);
        issueB(); cp_commit();
        stsA(0);
        cp_wait<0>();
        __syncthreads();
        for (int t = 0; t < T; t++) {
            int s = t & 1;
            if (t + 1 < T) loadAf32(t + 1);
            mmaStage(s, t);
            if (t + 1 < T) stsA(1 - s);
            __syncthreads();
        }
    } else {
        issueB(); issueApl(0, 0); cp_commit();
        if (T > 1) { issueApl(1, 1); cp_commit(); }
        for (int t = 0; t < T; t++) {
            if (t < T - 1) cp_wait<1>(); else cp_wait<0>();
            __syncthreads();
            mmaStage(t % 3, t);
            if (t + 2 < T) { issueApl(t + 2, (t + 2) % 3); cp_commit(); }
        }
    }

    // ---------------- epilogue ----------------
    if (MODE == 0) {
        #pragma unroll
        for (int i = 0; i < MT; i++) {
            int gr1 = row0 + rowW + i * 16 + gid;
            int gr2 = gr1 + 8;
            #pragma unroll
            for (int j = 0; j < NT; j++) {
                int c = colW + j * 8 + 2 * tig;
                float b0 = bias ? bias[c] : 0.0f;
                float b1 = bias ? bias[c + 1] : 0.0f;
                if (gr1 < M)
                    *(float2*)&C[(size_t)gr1 * BN + c] =
                        make_float2(acc[i][j][0] + b0, acc[i][j][1] + b1);
                if (gr2 < M)
                    *(float2*)&C[(size_t)gr2 * BN + c] =
                        make_float2(acc[i][j][2] + b0, acc[i][j][3] + b1);
            }
        }
    } else {
        #pragma unroll
        for (int i = 0; i < MT; i++) {
            int lr1 = rowW + i * 16 + gid, lr2 = lr1 + 8;
            int gr1 = row0 + lr1, gr2 = row0 + lr2;
            int sn1 = src[gr1], dn1 = dst[gr1];
            int sn2 = src[gr2], dn2 = dst[gr2];
            float sc1 = 0.0f, sc2 = 0.0f;
            #pragma unroll
            for (int j = 0; j < NT; j++) {
                int c = colW + j * 8 + 2 * tig;
                float b0 = bias[c], b1 = bias[c + 1];
                float2 xi1 = *(const float2*)&XNI[(size_t)sn1 * BN + c];
                float2 xj1 = *(const float2*)&XNJ[(size_t)dn1 * BN + c];
                float o0 = acc[i][j][0] + xi1.x + xj1.x + b0;
                float o1 = acc[i][j][1] + xi1.y + xj1.y + b1;
                o0 = o0 > 0.f ? o0 : 0.01f * o0;
                o1 = o1 > 0.f ? o1 : 0.01f * o1;
                float2 xi2 = *(const float2*)&XNI[(size_t)sn2 * BN + c];
                float2 xj2 = *(const float2*)&XNJ[(size_t)dn2 * BN + c];
                float p0 = acc[i][j][2] + xi2.x + xj2.x + b0;
                float p1 = acc[i][j][3] + xi2.y + xj2.y + b1;
                p0 = p0 > 0.f ? p0 : 0.01f * p0;
                p1 = p1 > 0.f ? p1 : 0.01f * p1;
                if (MODE == 1) {
                    *(uint32_t*)&Fhi[(size_t)gr1 * BN + c] = pk(o0, o1);
                    *(uint32_t*)&Flo[(size_t)gr1 * BN + c] = pk(o0 - bfe(o0), o1 - bfe(o1));
                    *(uint32_t*)&Fhi[(size_t)gr2 * BN + c] = pk(p0, p1);
                    *(uint32_t*)&Flo[(size_t)gr2 * BN + c] = pk(p0 - bfe(p0), p1 - bfe(p1));
                    float a0 = attn[c], a1 = attn[c + 1];
                    sc1 += o0 * a0 + o1 * a1;
                    sc2 += p0 * a0 + p1 * a1;
                } else {
                    *(float2*)&C[(size_t)gr1 * BN + c] = make_float2(o0, o1);
                    *(float2*)&C[(size_t)gr2 * BN + c] = make_float2(p0, p1);
                }
            }
            if (MODE == 1) {
                sc1 += __shfl_xor_sync(0xffffffffu, sc1, 1);
                sc1 += __shfl_xor_sync(0xffffffffu, sc1, 2);
                sc2 += __shfl_xor_sync(0xffffffffu, sc2, 1);
                sc2 += __shfl_xor_sync(0xffffffffu, sc2, 2);
                if (tig == 0) {
                    atomicAdd(&s_sc[lr1], sc1);
                    atomicAdd(&s_sc[lr2], sc2);
                }
            }
        }
        if (MODE == 1) {
            __syncthreads();
            if (tid < BM) score[row0 + tid] = s_sc[tid];
        }
    }
}

// ---------------- segment softmax over dst ----------------
__device__ __forceinline__ int enc_f(float f) {
    int i = __float_as_int(f);
    return i >= 0 ? i : (i ^ 0x7fffffff);
}
__device__ __forceinline__ float dec_f(int i) {
    return __int_as_float(i >= 0 ? i : (i ^ 0x7fffffff));
}

__global__ void seg_max(const float* __restrict__ score, const int* __restrict__ dst,
                        int* __restrict__ menc, int E) {
    int e = blockIdx.x * blockDim.x + threadIdx.x;
    if (e >= E) return;
    atomicMax(&menc[dst[e]], enc_f(score[e]));
}

__global__ void seg_expsum(const float* __restrict__ score, const int* __restrict__ dst,
                           const int* __restrict__ menc, float* __restrict__ ex,
                           float* __restrict__ ssum, int E) {
    int e = blockIdx.x * blockDim.x + threadIdx.x;
    if (e >= E) return;
    int d = dst[e];
    float ev = expf(score[e] - dec_f(menc[d]));
    ex[e] = ev;
    atomicAdd(&ssum[d], ev);
}

template<int DO>
__global__ void aggregate_k(const float* __restrict__ ex, const float* __restrict__ ssum,
                            const float* __restrict__ H, const int* __restrict__ src,
                            const int* __restrict__ dst, float* __restrict__ out, int E) {
    constexpr int L = DO / 4;
    long long gt = (long long)blockIdx.x * blockDim.x + threadIdx.x;
    int e = (int)(gt / L), l = (int)(gt % L);
    if (e >= E) return;
    int dn = dst[e];
    float a = ex[e] / ssum[dn];
    float4 h = *(const float4*)&H[(size_t)src[e] * DO + l * 4];
    float* p = &out[(size_t)dn * DO + l * 4];
    asm volatile("red.global.add.v4.f32 [%0], {%1,%2,%3,%4};"
                 :: "l"(p), "f"(h.x * a), "f"(h.y * a), "f"(h.z * a), "f"(h.w * a)
                 : "memory");
}

// ---------------- host ----------------
static inline constexpr int smemSz(int BN, int KT, int AF32) {
    return (AF32 ? 2 : 3) * 2 * 128 * 48 + 2 * BN * (KT * 2 + 16) + 512;
}

extern "C" void kernel_launch(void* const* d_in, const int* in_sizes, int n_in,
                              void* d_out, int out_size) {
    const float* x    = (const float*)d_in[0];
    const float* e    = (const float*)d_in[1];
    const int*   src  = (const int*)d_in[2];
    const int*   dst  = (const int*)d_in[3];

    const float* W_n1  = (const float*)d_in[4];
    const float* b_n1  = (const float*)d_in[5];
    const float* W_ni1 = (const float*)d_in[6];
    const float* W_nj1 = (const float*)d_in[7];
    const float* W_f1  = (const float*)d_in[8];
    const float* attn1 = (const float*)d_in[9];
    const float* bias1 = (const float*)d_in[10];

    const float* W_n2  = (const float*)d_in[11];
    const float* b_n2  = (const float*)d_in[12];
    const float* W_ni2 = (const float*)d_in[13];
    const float* W_nj2 = (const float*)d_in[14];
    const float* W_f2  = (const float*)d_in[15];
    const float* attn2 = (const float*)d_in[16];
    const float* bias2 = (const float*)d_in[17];

    const float* W_ni3 = (const float*)d_in[20];
    const float* W_nj3 = (const float*)d_in[21];
    const float* W_f3  = (const float*)d_in[22];
    const float* bias3 = (const float*)d_in[24];

    float* out = (float*)d_out;

    float *XNI, *XNJ, *H, *X2, *X3, *score, *ex, *ssum, *bn2, *bias2p, *attn2p;
    int* menc;
    __nv_bfloat16 *F1P, *F2P, *wts;
    cudaGetSymbolAddress((void**)&XNI, g_XNI);
    cudaGetSymbolAddress((void**)&XNJ, g_XNJ);
    cudaGetSymbolAddress((void**)&H,   g_H);
    cudaGetSymbolAddress((void**)&X2,  g_X2);
    cudaGetSymbolAddress((void**)&X3,  g_X3);
    cudaGetSymbolAddress((void**)&score, g_score);
    cudaGetSymbolAddress((void**)&ex,  g_ex);
    cudaGetSymbolAddress((void**)&ssum, g_ssum);
    cudaGetSymbolAddress((void**)&menc, g_menc);
    cudaGetSymbolAddress((void**)&bn2,  g_bn2);
    cudaGetSymbolAddress((void**)&bias2p, g_bias2);
    cudaGetSymbolAddress((void**)&attn2p, g_attn2);
    cudaGetSymbolAddress((void**)&F1P, g_F1P);
    cudaGetSymbolAddress((void**)&F2P, g_F2P);
    cudaGetSymbolAddress((void**)&wts, g_wts);

    const size_t ePN  = (size_t)EE * 128;
    const size_t F2PN = (size_t)EE * 32;
    const size_t WTN  = 4 * WL1 + 4 * WL2 + 3 * WL3;
    __nv_bfloat16 *wtH = wts, *wtL = wts + WTN;
    const int oWn1 = 0 * WL1, oWni1 = 1 * WL1, oWnj1 = 2 * WL1, oWf1 = 3 * WL1;
    const int base2 = 4 * WL1;
    const int oWn2 = base2, oWni2 = base2 + WL2, oWnj2 = base2 + 2 * WL2, oWf2 = base2 + 3 * WL2;
    const int base3 = base2 + 4 * WL2;
    const int oWni3 = base3, oWnj3 = base3 + WL3, oWf3 = base3 + 2 * WL3;

    const int Nn = NN, Ee = EE;
    const int nodeGrid = (Nn + 127) / 128;
    const int edgeGrid = Ee / 128;
    const int perThread = (Ee + 255) / 256;

    // opt-in smem sizes (>48KB instances)
    constexpr int S1  = smemSz(128, 128, 1);   // 94,720
    constexpr int S2n = smemSz(32, 128, 1);
    constexpr int S2e = smemSz(32, 128, 0);    // 54,784
    constexpr int S3n = smemSz(64, 32, 1);
    constexpr int S3e = smemSz(64, 32, 0);
    cudaFuncSetAttribute(gemm_pl<128, 128, 64, 32, 0, 1>, cudaFuncAttributeMaxDynamicSharedMemorySize, S1);
    cudaFuncSetAttribute(gemm_pl<128, 128, 64, 32, 1, 1>, cudaFuncAttributeMaxDynamicSharedMemorySize, S1);
    cudaFuncSetAttribute(gemm_pl<32, 128, 16, 32, 1, 0>, cudaFuncAttributeMaxDynamicSharedMemorySize, S2e);

    // ---- parameter prep ----
    VJobs vj;
    vj.j[0] = {b_n2,  bn2,    30, 32};
    vj.j[1] = {bias2, bias2p, 30, 32};
    vj.j[2] = {attn2, attn2p, 30, 32};
    pad_vec<<<dim3(1, 3), 32>>>(vj);

    WJobs wj;
    wj.j[0]  = {W_n1,  oWn1,  128, 128, 128, 128};
    wj.j[1]  = {W_ni1, oWni1, 128, 128, 128, 128};
    wj.j[2]  = {W_nj1, oWnj1, 128, 128, 128, 128};
    wj.j[3]  = {W_f1,  oWf1,  128, 128, 128, 128};
    wj.j[4]  = {W_n2,  oWn2,  128, 30, 128, 32};
    wj.j[5]  = {W_ni2, oWni2, 128, 30, 128, 32};
    wj.j[6]  = {W_nj2, oWnj2, 128, 30, 128, 32};
    wj.j[7]  = {W_f2,  oWf2,  128, 30, 128, 32};
    wj.j[8]  = {W_ni3, oWni3, 30, 64, 32, 64};
    wj.j[9]  = {W_nj3, oWnj3, 30, 64, 32, 64};
    wj.j[10] = {W_f3,  oWf3,  30, 64, 32, 64};
    conv_wt<<<dim3(64, 11), 256>>>(wj, wtH, wtL);

    // ================= Layer 1 =================
    gemm_pl<128, 128, 64, 32, 0, 1><<<nodeGrid, 256, S1>>>(x, nullptr, wtH + oWni1, wtL + oWni1,
        XNI, nullptr, nullptr, nullptr, nullptr, nullptr, nullptr, nullptr, nullptr, nullptr, Nn);
    gemm_pl<128, 128, 64, 32, 0, 1><<<nodeGrid, 256, S1>>>(x, nullptr, wtH + oWnj1, wtL + oWnj1,
        XNJ, nullptr, nullptr, nullptr, nullptr, nullptr, nullptr, nullptr, nullptr, nullptr, Nn);
    gemm_pl<128, 128, 64, 32, 0, 1><<<nodeGrid, 256, S1>>>(x, nullptr, wtH + oWn1, wtL + oWn1,
        H, nullptr, nullptr, b_n1, nullptr, nullptr, nullptr, nullptr, nullptr, nullptr, Nn);
    gemm_pl<128, 128, 64, 32, 1, 1><<<edgeGrid, 256, S1>>>(e, nullptr, wtH + oWf1, wtL + oWf1,
        nullptr, F1P, F1P + ePN, bias1, XNI, XNJ, src, dst, attn1, score, Ee);

    cudaMemsetAsync(menc, 0x80, (size_t)Nn * sizeof(int), 0);
    cudaMemsetAsync(ssum, 0,    (size_t)Nn * sizeof(float), 0);
    cudaMemsetAsync(X2,   0,    (size_t)Nn * 128 * sizeof(float), 0);
    seg_max<<<perThread, 256>>>(score, dst, menc, Ee);
    seg_expsum<<<perThread, 256>>>(score, dst, menc, ex, ssum, Ee);
    aggregate_k<128><<<((long long)Ee * 32 + 255) / 256, 256>>>(ex, ssum, H, src, dst, X2, Ee);

    // ================= Layer 2 =================
    gemm_pl<32, 128, 16, 32, 0, 1><<<nodeGrid, 256, S2n>>>(X2, nullptr, wtH + oWni2, wtL + oWni2,
        XNI, nullptr, nullptr, nullptr, nullptr, nullptr, nullptr, nullptr, nullptr, nullptr, Nn);
    gemm_pl<32, 128, 16, 32, 0, 1><<<nodeGrid, 256, S2n>>>(X2, nullptr, wtH + oWnj2, wtL + oWnj2,
        XNJ, nullptr, nullptr, nullptr, nullptr, nullptr, nullptr, nullptr, nullptr, nullptr, Nn);
    gemm_pl<32, 128, 16, 32, 0, 1><<<nodeGrid, 256, S2n>>>(X2, nullptr, wtH + oWn2, wtL + oWn2,
        H, nullptr, nullptr, bn2, nullptr, nullptr, nullptr, nullptr, nullptr, nullptr, Nn);
    gemm_pl<32, 128, 16, 32, 1, 0><<<edgeGrid, 256, S2e>>>(F1P, F1P + ePN, wtH + oWf2, wtL + oWf2,
        nullptr, F2P, F2P + F2PN, bias2p, XNI, XNJ, src, dst, attn2p, score, Ee);

    cudaMemsetAsync(menc, 0x80, (size_t)Nn * sizeof(int), 0);
    cudaMemsetAsync(ssum, 0,    (size_t)Nn * sizeof(float), 0);
    cudaMemsetAsync(X3,   0,    (size_t)Nn * 32 * sizeof(float), 0);
    seg_max<<<perThread, 256>>>(score, dst, menc, Ee);
    seg_expsum<<<perThread, 256>>>(score, dst, menc, ex, ssum, Ee);
    aggregate_k<32><<<((long long)Ee * 8 + 255) / 256, 256>>>(ex, ssum, H, src, dst, X3, Ee);

    // ================= Layer 3 (only f) =================
    gemm_pl<64, 32, 32, 32, 0, 1><<<nodeGrid, 256, S3n>>>(X3, nullptr, wtH + oWni3, wtL + oWni3,
        XNI, nullptr, nullptr, nullptr, nullptr, nullptr, nullptr, nullptr, nullptr, nullptr, Nn);
    gemm_pl<64, 32, 32, 32, 0, 1><<<nodeGrid, 256, S3n>>>(X3, nullptr, wtH + oWnj3, wtL + oWnj3,
        XNJ, nullptr, nullptr, nullptr, nullptr, nullptr, nullptr, nullptr, nullptr, nullptr, Nn);
    gemm_pl<64, 32, 32, 32, 2, 0><<<edgeGrid, 256, S3e>>>(F2P, F2P + F2PN, wtH + oWf3, wtL + oWf3,
        out, nullptr, nullptr, bias3, XNI, XNJ, src, dst, nullptr, nullptr, Ee);

    (void)in_sizes; (void)n_in; (void)out_size;
}